// round 1
// baseline (speedup 1.0000x reference)
#include <cuda_runtime.h>
#include <cstdint>

#define NPTS 32768
#define DH 32
#define NH 8
#define NC 3
#define BSZ 128
#define NBK 256
#define CHN 24          // NC*NH
#define QSTR 36         // padded row stride for 35-dim hat vectors

typedef unsigned long long ull;

// ---------------- scratch (static device globals; no allocations) ----------------
__device__ float g_qhat[(size_t)NH * NPTS * QSTR];
__device__ float g_khat[(size_t)NH * NPTS * QSTR];
__device__ float g_v[(size_t)NH * NPTS * DH];
__device__ float g_qh[(size_t)CHN * NPTS];
__device__ float g_kh[(size_t)CHN * NPTS];
__device__ ull   g_keys[(size_t)2 * CHN * NPTS];
__device__ unsigned g_mn[CHN], g_mx[CHN];
__device__ float g_hs[CHN];
__device__ float g_sqrtw[NH * 3];
__device__ float g_oscr[(size_t)CHN * NPTS * DH];   // scattered per-c outputs
__device__ float g_dscr[(size_t)CHN * NPTS];        // scattered per-c denominators
__device__ float g_attn[(size_t)NPTS * 256];        // normalized attention output [n][h*32+d]

// ---------------- helpers ----------------
__device__ __forceinline__ unsigned encf(float f) {
    unsigned u = __float_as_uint(f);
    return (u & 0x80000000u) ? ~u : (u | 0x80000000u);
}
__device__ __forceinline__ float decf(unsigned u) {
    return (u & 0x80000000u) ? __uint_as_float(u ^ 0x80000000u)
                             : __uint_as_float(~u);
}

// fast exp on FMA pipe (avoids MUFU bottleneck): rel err ~1e-7, valid |x|<=87
__device__ __forceinline__ float fexp(float x) {
    x = fminf(fmaxf(x, -87.0f), 87.0f);
    float t = fmaf(x, 1.4426950408889634f, 12582912.0f);
    float j = t - 12582912.0f;
    float f = fmaf(j, -0.693145751953125f, x);
    f = fmaf(j, -1.4286067653301938e-6f, f);
    float p = 1.3888889e-3f;
    p = fmaf(p, f, 8.3333333e-3f);
    p = fmaf(p, f, 4.1666667e-2f);
    p = fmaf(p, f, 1.6666667e-1f);
    p = fmaf(p, f, 0.5f);
    p = fmaf(p, f, 1.0f);
    p = fmaf(p, f, 1.0f);
    return __int_as_float(__float_as_int(p) + (__float_as_int(t) << 23));
}

// ---------------- kernel 0: RPE weights + minmax init ----------------
__global__ void k_prep(const float* __restrict__ wr) {
    int t = threadIdx.x;
    if (t < CHN) {
        g_mn[t] = 0xFFFFFFFFu;
        g_mx[t] = 0u;
        int h = t / 3, r = t % 3;
        float qw = 0.f;
        for (int k = 0; k < 8; k++) {
            float s = 0.f;
            for (int d = 0; d < 32; d++) s += wr[(h * 32 + d) * 24 + r * 8 + k];
            qw += expf(fminf(s, 50.f));
        }
        g_sqrtw[t] = sqrtf(2.f * qw);
    }
}

// ---------------- kernel 1: LayerNorm + QKV projection ----------------
// 768 threads/block: thread j owns one output column (W column in registers),
// xn rows broadcast from smem. Stores are warp-coalesced.
__global__ void __launch_bounds__(768) k_ln_qkv(
    const float* __restrict__ x, const float* __restrict__ n1w,
    const float* __restrict__ n1b, const float* __restrict__ wq,
    const float* __restrict__ wk, const float* __restrict__ wv) {
    __shared__ float xs[128 * QSTR];
    int base = blockIdx.x * 128;
    int tid = threadIdx.x;
    if (tid < 128) {
        int n = base + tid;
        float r[32];
        const float4* xr = (const float4*)(x + (size_t)n * 32);
#pragma unroll
        for (int u = 0; u < 8; u++) {
            float4 v4 = xr[u];
            r[4 * u] = v4.x; r[4 * u + 1] = v4.y; r[4 * u + 2] = v4.z; r[4 * u + 3] = v4.w;
        }
        float mu = 0.f;
#pragma unroll
        for (int d = 0; d < 32; d++) mu += r[d];
        mu *= (1.0f / 32.0f);
        float var = 0.f;
#pragma unroll
        for (int d = 0; d < 32; d++) { float dd = r[d] - mu; var += dd * dd; }
        var *= (1.0f / 32.0f);
        float rs = rsqrtf(var + 1e-5f);
#pragma unroll
        for (int d = 0; d < 32; d++)
            xs[tid * QSTR + d] = (r[d] - mu) * rs * n1w[d] + n1b[d];
    }
    __syncthreads();
    int j = tid;                 // 0..767
    int proj = j >> 8, jj = j & 255;
    const float* W = (proj == 0) ? wq : (proj == 1) ? wk : wv;
    float wc[32];
#pragma unroll
    for (int d = 0; d < 32; d++) wc[d] = W[d * 256 + jj];
    int h = jj >> 5, d0 = jj & 31;
    float* dst;
    int stride;
    if (proj == 0) { dst = g_qhat; stride = QSTR; }
    else if (proj == 1) { dst = g_khat; stride = QSTR; }
    else { dst = g_v; stride = DH; }
    for (int r = 0; r < 128; r++) {
        float acc = 0.f;
        const float4* xr = (const float4*)(xs + r * QSTR);
#pragma unroll
        for (int u = 0; u < 8; u++) {
            float4 v4 = xr[u];
            acc += v4.x * wc[4 * u] + v4.y * wc[4 * u + 1] + v4.z * wc[4 * u + 2] + v4.w * wc[4 * u + 3];
        }
        int n = base + r;
        dst[((size_t)h * NPTS + n) * stride + d0] = acc;
    }
}

// ---------------- kernel 2: q_hat/k_hat tails + LSH hashes + min/max ----------------
__global__ void k_hash(const float* __restrict__ coords, const float* __restrict__ alpha) {
    int h = blockIdx.y;
    int n = blockIdx.x * 256 + threadIdx.x;
    float q[36], kk[36];
    float* qrow = g_qhat + ((size_t)h * NPTS + n) * QSTR;
    float* krow = g_khat + ((size_t)h * NPTS + n) * QSTR;
#pragma unroll
    for (int u = 0; u < 8; u++) {
        ((float4*)q)[u] = ((const float4*)qrow)[u];
        ((float4*)kk)[u] = ((const float4*)krow)[u];
    }
#pragma unroll
    for (int r = 0; r < 3; r++) {
        float sr = g_sqrtw[h * 3 + r] * coords[n * 3 + r];
        q[32 + r] = sr; kk[32 + r] = sr;
        qrow[32 + r] = sr; krow[32 + r] = sr;
    }
    float qh[3] = {0.f, 0.f, 0.f}, kh[3] = {0.f, 0.f, 0.f};
    const float* al = alpha + h * 105;
#pragma unroll 5
    for (int d = 0; d < 35; d++) {
        float a0 = al[d * 3 + 0], a1 = al[d * 3 + 1], a2 = al[d * 3 + 2];
        qh[0] += q[d] * a0; qh[1] += q[d] * a1; qh[2] += q[d] * a2;
        kh[0] += kk[d] * a0; kh[1] += kk[d] * a1; kh[2] += kk[d] * a2;
    }
#pragma unroll
    for (int c = 0; c < 3; c++) {
        g_qh[(size_t)(c * 8 + h) * NPTS + n] = qh[c];
        g_kh[(size_t)(c * 8 + h) * NPTS + n] = kh[c];
        float mn = fminf(qh[c], kh[c]);
        float mx = fmaxf(qh[c], kh[c]);
#pragma unroll
        for (int o = 16; o > 0; o >>= 1) {
            mn = fminf(mn, __shfl_xor_sync(0xFFFFFFFFu, mn, o));
            mx = fmaxf(mx, __shfl_xor_sync(0xFFFFFFFFu, mx, o));
        }
        if ((threadIdx.x & 31) == 0) {
            atomicMin(&g_mn[c * 8 + h], encf(mn));
            atomicMax(&g_mx[c * 8 + h], encf(mx));
        }
    }
}

// ---------------- kernel 3: hash shift ----------------
__global__ void k_hs() {
    int t = threadIdx.x;
    if (t < CHN) g_hs[t] = decf(g_mx[t]) - decf(g_mn[t]);
}

// ---------------- kernel 4: build 64-bit sort keys ----------------
__global__ void k_keys(const int* __restrict__ shifts) {
    int t = blockIdx.x * 256 + threadIdx.x;       // < CHN*NPTS
    int seg = t >> 15;
    int n = t & (NPTS - 1);
    float hsv = g_hs[seg];
    float sh = (float)shifts[t];
    float off = __fmul_rn(sh, hsv);                // match XLA: mul then add, no FMA
    g_keys[t] = ((ull)encf(__fadd_rn(g_qh[t], off)) << 32) | (unsigned)n;
    g_keys[(size_t)CHN * NPTS + t] =
        ((ull)encf(__fadd_rn(g_kh[t], off)) << 32) | (unsigned)n;
}

// ---------------- bitonic sort (48 segments of 32768, stable via packed index) ----------------
__global__ void __launch_bounds__(512) k_sort_local() {
    __shared__ ull s[4096];
    int chunk = blockIdx.x;                       // 384 chunks; 8 per segment
    size_t base = (size_t)chunk * 4096;
    int isb = (chunk & 7) * 4096;                 // index-within-segment base
    for (int p = threadIdx.x; p < 4096; p += 512) s[p] = g_keys[base + p];
    for (int k = 2; k <= 4096; k <<= 1) {
        for (int j = k >> 1; j >= 1; j >>= 1) {
            __syncthreads();
#pragma unroll
            for (int p = 0; p < 4; p++) {
                int t = threadIdx.x + p * 512;
                int i = ((t & ~(j - 1)) << 1) | (t & (j - 1));
                bool up = (((isb + i) & k) == 0);
                ull a = s[i], b = s[i + j];
                if ((a > b) == up) { s[i] = b; s[i + j] = a; }
            }
        }
    }
    __syncthreads();
    for (int p = threadIdx.x; p < 4096; p += 512) g_keys[base + p] = s[p];
}

__global__ void k_sort_ce(int k, int j) {
    int t = blockIdx.x * 256 + threadIdx.x;       // 2*CHN*16384 CEs
    int seg = t >> 14;
    int tl = t & 16383;
    int i = ((tl & ~(j - 1)) << 1) | (tl & (j - 1));
    size_t gi = (size_t)seg * NPTS + i;
    bool up = ((i & k) == 0);
    ull a = g_keys[gi], b = g_keys[gi + j];
    if ((a > b) == up) { g_keys[gi] = b; g_keys[gi + j] = a; }
}

__global__ void __launch_bounds__(512) k_sort_merge(int k) {
    __shared__ ull s[4096];
    int chunk = blockIdx.x;
    size_t base = (size_t)chunk * 4096;
    int isb = (chunk & 7) * 4096;
    for (int p = threadIdx.x; p < 4096; p += 512) s[p] = g_keys[base + p];
    for (int j = 2048; j >= 1; j >>= 1) {
        __syncthreads();
#pragma unroll
        for (int p = 0; p < 4; p++) {
            int t = threadIdx.x + p * 512;
            int i = ((t & ~(j - 1)) << 1) | (t & (j - 1));
            bool up = (((isb + i) & k) == 0);
            ull a = s[i], b = s[i + j];
            if ((a > b) == up) { s[i] = b; s[i + j] = a; }
        }
    }
    __syncthreads();
    for (int p = threadIdx.x; p < 4096; p += 512) g_keys[base + p] = s[p];
}

// ---------------- kernel 5: bucketed kernelized attention ----------------
__global__ void __launch_bounds__(128) k_attn() {
    __shared__ float ks[BSZ][QSTR];
    __shared__ float vsm[BSZ][DH];
    __shared__ float ksq[BSZ];
    int seg = blockIdx.y, b = blockIdx.x, i = threadIdx.x;
    int h = seg & 7;

    unsigned kidx = (unsigned)g_keys[((size_t)(CHN + seg)) * NPTS + b * BSZ + i];
    float tmp[36];
    const float4* kr = (const float4*)(g_khat + ((size_t)h * NPTS + kidx) * QSTR);
#pragma unroll
    for (int u = 0; u < 9; u++) ((float4*)tmp)[u] = kr[u];
    float s2 = 0.f;
#pragma unroll
    for (int d = 0; d < 35; d++) s2 += tmp[d] * tmp[d];
    ksq[i] = -0.5f * s2;
#pragma unroll
    for (int u = 0; u < 9; u++) ((float4*)&ks[i][0])[u] = ((float4*)tmp)[u];
    const float4* vr = (const float4*)(g_v + ((size_t)h * NPTS + kidx) * DH);
#pragma unroll
    for (int u = 0; u < 8; u++) ((float4*)&vsm[i][0])[u] = vr[u];

    unsigned qidx = (unsigned)g_keys[(size_t)seg * NPTS + b * BSZ + i];
    float q[36];
    const float4* qr = (const float4*)(g_qhat + ((size_t)h * NPTS + qidx) * QSTR);
#pragma unroll
    for (int u = 0; u < 9; u++) ((float4*)q)[u] = qr[u];
    float qs2 = 0.f;
#pragma unroll
    for (int d = 0; d < 35; d++) qs2 += q[d] * q[d];
    float qsq = -0.5f * qs2;

    float acc[32];
#pragma unroll
    for (int d = 0; d < 32; d++) acc[d] = 0.f;
    float den = 0.f;
    __syncthreads();

    for (int j = 0; j < BSZ; j++) {
        const float* kj = &ks[j][0];
        float s = qsq + ksq[j];
#pragma unroll
        for (int d = 0; d < 35; d++) s += q[d] * kj[d];
        float e = fexp(fminf(s, 0.f));
        den += e;
        const float* vj = &vsm[j][0];
#pragma unroll
        for (int d = 0; d < 32; d++) acc[d] += e * vj[d];
    }
    float* od = g_oscr + ((size_t)seg * NPTS + qidx) * DH;
#pragma unroll
    for (int u = 0; u < 8; u++)
        ((float4*)od)[u] = make_float4(acc[4 * u], acc[4 * u + 1], acc[4 * u + 2], acc[4 * u + 3]);
    g_dscr[(size_t)seg * NPTS + qidx] = den;
}

// ---------------- kernel 6: combine over hashes + normalize ----------------
__global__ void k_combine() {
    int t = blockIdx.x * 256 + threadIdx.x;   // NH*NPTS*8 threads
    int p = t & 7;
    int n = (t >> 3) & (NPTS - 1);
    int h = t >> 18;
    float den = g_dscr[(size_t)(0 + h) * NPTS + n] +
                g_dscr[(size_t)(8 + h) * NPTS + n] +
                g_dscr[(size_t)(16 + h) * NPTS + n] + 3e-20f;
    float4 a = ((const float4*)(g_oscr + ((size_t)(0 + h) * NPTS + n) * DH))[p];
    float4 b4 = ((const float4*)(g_oscr + ((size_t)(8 + h) * NPTS + n) * DH))[p];
    float4 c4 = ((const float4*)(g_oscr + ((size_t)(16 + h) * NPTS + n) * DH))[p];
    float inv = 1.0f / den;
    float4 o;
    o.x = (a.x + b4.x + c4.x) * inv;
    o.y = (a.y + b4.y + c4.y) * inv;
    o.z = (a.z + b4.z + c4.z) * inv;
    o.w = (a.w + b4.w + c4.w) * inv;
    ((float4*)(g_attn + (size_t)n * 256 + h * 32))[p] = o;
}

// ---------------- kernel 7: out-proj + residual + LN2 + FF(silu) + residual ----------------
__global__ void __launch_bounds__(128) k_epilogue(
    const float* __restrict__ x, const float* __restrict__ ow,
    const float* __restrict__ ob, const float* __restrict__ n2w,
    const float* __restrict__ n2b, const float* __restrict__ f1w,
    const float* __restrict__ f1b, const float* __restrict__ f2w,
    const float* __restrict__ f2b, float* __restrict__ out) {
    __shared__ float ws[256 * 32];
    __shared__ float f1s[32 * 32];
    __shared__ float f2s[32 * 32];
    __shared__ float cs[32 * 5];
    int tid = threadIdx.x;
    for (int i = tid; i < 8192; i += 128) ws[i] = ow[i];
    for (int i = tid; i < 1024; i += 128) { f1s[i] = f1w[i]; f2s[i] = f2w[i]; }
    if (tid < 32) {
        cs[tid] = ob[tid]; cs[32 + tid] = n2w[tid]; cs[64 + tid] = n2b[tid];
        cs[96 + tid] = f1b[tid]; cs[128 + tid] = f2b[tid];
    }
    __syncthreads();
    int n = blockIdx.x * 128 + tid;

    float acc[32];
#pragma unroll
    for (int d = 0; d < 32; d++) acc[d] = cs[d];
    const float4* ar = (const float4*)(g_attn + (size_t)n * 256);
    for (int jb = 0; jb < 64; jb++) {
        float4 a = ar[jb];
        float av[4] = {a.x, a.y, a.z, a.w};
        int j0 = jb * 4;
#pragma unroll
        for (int u = 0; u < 4; u++) {
            const float4* wr = (const float4*)(ws + (j0 + u) * 32);
            float v = av[u];
#pragma unroll
            for (int d4 = 0; d4 < 8; d4++) {
                float4 w4 = wr[d4];
                acc[4 * d4] += v * w4.x;
                acc[4 * d4 + 1] += v * w4.y;
                acc[4 * d4 + 2] += v * w4.z;
                acc[4 * d4 + 3] += v * w4.w;
            }
        }
    }
    // residual 1
    float x2[32];
    const float4* xr = (const float4*)(x + (size_t)n * 32);
#pragma unroll
    for (int u = 0; u < 8; u++) {
        float4 xv = xr[u];
        x2[4 * u] = xv.x + acc[4 * u];
        x2[4 * u + 1] = xv.y + acc[4 * u + 1];
        x2[4 * u + 2] = xv.z + acc[4 * u + 2];
        x2[4 * u + 3] = xv.w + acc[4 * u + 3];
    }
    // LN2
    float mu = 0.f;
#pragma unroll
    for (int d = 0; d < 32; d++) mu += x2[d];
    mu *= (1.0f / 32.0f);
    float var = 0.f;
#pragma unroll
    for (int d = 0; d < 32; d++) { float dd = x2[d] - mu; var += dd * dd; }
    var *= (1.0f / 32.0f);
    float rs = rsqrtf(var + 1e-5f);
    float xn2[32];
#pragma unroll
    for (int d = 0; d < 32; d++)
        xn2[d] = (x2[d] - mu) * rs * cs[32 + d] + cs[64 + d];
    // FF1 + silu
    float h1[32];
#pragma unroll 4
    for (int jj = 0; jj < 32; jj++) {
        float t2 = cs[96 + jj];
#pragma unroll
        for (int d = 0; d < 32; d++) t2 += xn2[d] * f1s[d * 32 + jj];
        h1[jj] = t2 / (1.0f + fexp(-t2));
    }
    // FF2 + residual 2
    float o[32];
#pragma unroll
    for (int d = 0; d < 32; d++) o[d] = cs[128 + d];
#pragma unroll 4
    for (int jj = 0; jj < 32; jj++) {
        float hv = h1[jj];
#pragma unroll
        for (int d = 0; d < 32; d++) o[d] += hv * f2s[jj * 32 + d];
    }
    float4* orow = (float4*)(out + (size_t)n * 32);
#pragma unroll
    for (int u = 0; u < 8; u++)
        orow[u] = make_float4(x2[4 * u] + o[4 * u], x2[4 * u + 1] + o[4 * u + 1],
                              x2[4 * u + 2] + o[4 * u + 2], x2[4 * u + 3] + o[4 * u + 3]);
}

// ---------------- launcher ----------------
extern "C" void kernel_launch(void* const* d_in, const int* in_sizes, int n_in,
                              void* d_out, int out_size) {
    const float* x = (const float*)d_in[0];
    const float* coords = (const float*)d_in[1];
    const int* shifts = (const int*)d_in[2];
    const float* n1w = (const float*)d_in[3];
    const float* n1b = (const float*)d_in[4];
    const float* wq = (const float*)d_in[5];
    const float* wk = (const float*)d_in[6];
    const float* wv = (const float*)d_in[7];
    const float* wr = (const float*)d_in[8];
    const float* alpha = (const float*)d_in[9];
    const float* ow = (const float*)d_in[10];
    const float* ob = (const float*)d_in[11];
    const float* n2w = (const float*)d_in[12];
    const float* n2b = (const float*)d_in[13];
    const float* f1w = (const float*)d_in[14];
    const float* f1b = (const float*)d_in[15];
    const float* f2w = (const float*)d_in[16];
    const float* f2b = (const float*)d_in[17];
    float* out = (float*)d_out;

    k_prep<<<1, 32>>>(wr);
    k_ln_qkv<<<NPTS / 128, 768>>>(x, n1w, n1b, wq, wk, wv);
    k_hash<<<dim3(NPTS / 256, NH), 256>>>(coords, alpha);
    k_hs<<<1, 32>>>();
    k_keys<<<(CHN * NPTS) / 256, 256>>>(shifts);

    // bitonic sort: 48 segments x 32768, stable (index packed in low bits)
    k_sort_local<<<2 * CHN * NPTS / 4096, 512>>>();
    k_sort_ce<<<(2 * CHN * NPTS / 2) / 256, 256>>>(8192, 4096);
    k_sort_merge<<<2 * CHN * NPTS / 4096, 512>>>(8192);
    k_sort_ce<<<(2 * CHN * NPTS / 2) / 256, 256>>>(16384, 8192);
    k_sort_ce<<<(2 * CHN * NPTS / 2) / 256, 256>>>(16384, 4096);
    k_sort_merge<<<2 * CHN * NPTS / 4096, 512>>>(16384);
    k_sort_ce<<<(2 * CHN * NPTS / 2) / 256, 256>>>(32768, 16384);
    k_sort_ce<<<(2 * CHN * NPTS / 2) / 256, 256>>>(32768, 8192);
    k_sort_ce<<<(2 * CHN * NPTS / 2) / 256, 256>>>(32768, 4096);
    k_sort_merge<<<2 * CHN * NPTS / 4096, 512>>>(32768);

    k_attn<<<dim3(NBK, CHN), 128>>>();
    k_combine<<<(NH * NPTS * 8) / 256, 256>>>();
    k_epilogue<<<NPTS / 128, 128>>>(x, ow, ob, n2w, n2b, f1w, f1b, f2w, f2b, out);
}

// round 2
// speedup vs baseline: 1.1914x; 1.1914x over previous
#include <cuda_runtime.h>
#include <cstdint>

#define NPTS 32768
#define DH 32
#define NH 8
#define NC 3
#define BSZ 128
#define NBK 256
#define CHN 24          // NC*NH
#define QSTR 36         // padded row stride for 35-dim hat vectors

typedef unsigned long long ull;

// ---------------- scratch (static device globals; no allocations) ----------------
__device__ float g_qhat[(size_t)NH * NPTS * QSTR];
__device__ float g_khat[(size_t)NH * NPTS * QSTR];
__device__ float g_v[(size_t)NH * NPTS * DH];
__device__ float g_qh[(size_t)CHN * NPTS];
__device__ float g_kh[(size_t)CHN * NPTS];
__device__ ull   g_keys[(size_t)2 * CHN * NPTS];
__device__ unsigned g_mn[CHN], g_mx[CHN];
__device__ float g_hs[CHN];
__device__ float g_sqrtw[NH * 3];
__device__ float g_oscr[(size_t)CHN * NPTS * DH];
__device__ float g_dscr[(size_t)CHN * NPTS];
__device__ float g_attn[(size_t)NPTS * 256];

// ---------------- f32x2 packed helpers ----------------
__device__ __forceinline__ ull pk2(float a, float b) {
    ull r; asm("mov.b64 %0, {%1, %2};" : "=l"(r) : "f"(a), "f"(b)); return r;
}
__device__ __forceinline__ void upk(ull p, float& a, float& b) {
    asm("mov.b64 {%0, %1}, %2;" : "=f"(a), "=f"(b) : "l"(p));
}
__device__ __forceinline__ ull f2fma(ull a, ull b, ull c) {
    ull d; asm("fma.rn.f32x2 %0, %1, %2, %3;" : "=l"(d) : "l"(a), "l"(b), "l"(c)); return d;
}
__device__ __forceinline__ ull f2add(ull a, ull b) {
    ull d; asm("add.rn.f32x2 %0, %1, %2;" : "=l"(d) : "l"(a), "l"(b)); return d;
}
__device__ __forceinline__ ull lo2(float4 v) { return pk2(v.x, v.y); }
__device__ __forceinline__ ull hi2(float4 v) { return pk2(v.z, v.w); }

// ---------------- sort helpers ----------------
__device__ __forceinline__ unsigned encf(float f) {
    unsigned u = __float_as_uint(f);
    return (u & 0x80000000u) ? ~u : (u | 0x80000000u);
}
__device__ __forceinline__ float decf(unsigned u) {
    return (u & 0x80000000u) ? __uint_as_float(u ^ 0x80000000u)
                             : __uint_as_float(~u);
}

// scalar fast exp on FMA pipe; clamped, rel err ~1e-7
__device__ __forceinline__ float fexp(float x) {
    x = fminf(fmaxf(x, -87.0f), 87.0f);
    float t = fmaf(x, 1.4426950408889634f, 12582912.0f);
    float j = t - 12582912.0f;
    float f = fmaf(j, -0.693145751953125f, x);
    f = fmaf(j, -1.4286067653301938e-6f, f);
    float p = 1.3888889e-3f;
    p = fmaf(p, f, 8.3333333e-3f);
    p = fmaf(p, f, 4.1666667e-2f);
    p = fmaf(p, f, 1.6666667e-1f);
    p = fmaf(p, f, 0.5f);
    p = fmaf(p, f, 1.0f);
    p = fmaf(p, f, 1.0f);
    return __int_as_float(__float_as_int(p) + (__float_as_int(t) << 23));
}

// packed exp for x <= ~0 (no upper clamp needed); underflow-guarded below j=-120
__device__ __forceinline__ void fexp2p(ull x2, float& e0, float& e1) {
    const ull L2E = pk2(1.4426950408889634f, 1.4426950408889634f);
    const ull MAG = pk2(12582912.0f, 12582912.0f);
    const ull NMAG = pk2(-12582912.0f, -12582912.0f);
    ull t2 = f2fma(x2, L2E, MAG);
    ull j2 = f2add(t2, NMAG);
    ull f2 = f2fma(j2, pk2(-0.693145751953125f, -0.693145751953125f), x2);
    f2 = f2fma(j2, pk2(-1.4286067653301938e-6f, -1.4286067653301938e-6f), f2);
    ull p = pk2(1.3888889e-3f, 1.3888889e-3f);
    p = f2fma(p, f2, pk2(8.3333333e-3f, 8.3333333e-3f));
    p = f2fma(p, f2, pk2(4.1666667e-2f, 4.1666667e-2f));
    p = f2fma(p, f2, pk2(1.6666667e-1f, 1.6666667e-1f));
    p = f2fma(p, f2, pk2(0.5f, 0.5f));
    p = f2fma(p, f2, pk2(1.0f, 1.0f));
    p = f2fma(p, f2, pk2(1.0f, 1.0f));
    float p0, p1, t0, t1;
    upk(p, p0, p1); upk(t2, t0, t1);
    float r0 = __int_as_float(__float_as_int(p0) + (__float_as_int(t0) << 23));
    float r1 = __int_as_float(__float_as_int(p1) + (__float_as_int(t1) << 23));
    e0 = (t0 < 12582792.0f) ? 0.0f : r0;   // j < -120 -> 0
    e1 = (t1 < 12582792.0f) ? 0.0f : r1;
}

// ---------------- kernel 0: RPE weights + minmax init ----------------
__global__ void k_prep(const float* __restrict__ wr) {
    int t = threadIdx.x;
    if (t < CHN) {
        g_mn[t] = 0xFFFFFFFFu;
        g_mx[t] = 0u;
        int h = t / 3, r = t % 3;
        float qw = 0.f;
        for (int k = 0; k < 8; k++) {
            float s = 0.f;
            for (int d = 0; d < 32; d++) s += wr[(h * 32 + d) * 24 + r * 8 + k];
            qw += expf(fminf(s, 50.f));
        }
        g_sqrtw[t] = sqrtf(2.f * qw);
    }
}

// ---------------- kernel 1: LayerNorm + QKV projection (packed) ----------------
__global__ void __launch_bounds__(768) k_ln_qkv(
    const float* __restrict__ x, const float* __restrict__ n1w,
    const float* __restrict__ n1b, const float* __restrict__ wq,
    const float* __restrict__ wk, const float* __restrict__ wv) {
    __shared__ float xs[128 * QSTR];
    int base = blockIdx.x * 128;
    int tid = threadIdx.x;
    if (tid < 128) {
        int n = base + tid;
        float r[32];
        const float4* xr = (const float4*)(x + (size_t)n * 32);
#pragma unroll
        for (int u = 0; u < 8; u++) {
            float4 v4 = xr[u];
            r[4 * u] = v4.x; r[4 * u + 1] = v4.y; r[4 * u + 2] = v4.z; r[4 * u + 3] = v4.w;
        }
        float mu = 0.f;
#pragma unroll
        for (int d = 0; d < 32; d++) mu += r[d];
        mu *= (1.0f / 32.0f);
        float var = 0.f;
#pragma unroll
        for (int d = 0; d < 32; d++) { float dd = r[d] - mu; var += dd * dd; }
        var *= (1.0f / 32.0f);
        float rs = rsqrtf(var + 1e-5f);
#pragma unroll
        for (int d = 0; d < 32; d++)
            xs[tid * QSTR + d] = (r[d] - mu) * rs * n1w[d] + n1b[d];
    }
    __syncthreads();
    int j = tid;
    int proj = j >> 8, jj = j & 255;
    const float* W = (proj == 0) ? wq : (proj == 1) ? wk : wv;
    ull wpk[16];
#pragma unroll
    for (int d = 0; d < 16; d++)
        wpk[d] = pk2(W[(2 * d) * 256 + jj], W[(2 * d + 1) * 256 + jj]);
    int h = jj >> 5, d0 = jj & 31;
    float* dst;
    int stride;
    if (proj == 0) { dst = g_qhat; stride = QSTR; }
    else if (proj == 1) { dst = g_khat; stride = QSTR; }
    else { dst = g_v; stride = DH; }
    for (int r = 0; r < 128; r++) {
        const float4* xr = (const float4*)(xs + r * QSTR);
        ull a0 = 0, a1 = 0;
#pragma unroll
        for (int u = 0; u < 8; u++) {
            float4 v4 = xr[u];
            a0 = f2fma(lo2(v4), wpk[2 * u], a0);
            a1 = f2fma(hi2(v4), wpk[2 * u + 1], a1);
        }
        float s0, s1;
        upk(f2add(a0, a1), s0, s1);
        dst[((size_t)h * NPTS + (base + r)) * stride + d0] = s0 + s1;
    }
}

// ---------------- kernel 2: hat tails + LSH hashes + min/max ----------------
__global__ void k_hash(const float* __restrict__ coords, const float* __restrict__ alpha) {
    int h = blockIdx.y;
    int n = blockIdx.x * 256 + threadIdx.x;
    float q[36], kk[36];
    float* qrow = g_qhat + ((size_t)h * NPTS + n) * QSTR;
    float* krow = g_khat + ((size_t)h * NPTS + n) * QSTR;
#pragma unroll
    for (int u = 0; u < 8; u++) {
        ((float4*)q)[u] = ((const float4*)qrow)[u];
        ((float4*)kk)[u] = ((const float4*)krow)[u];
    }
#pragma unroll
    for (int r = 0; r < 3; r++) {
        float sr = g_sqrtw[h * 3 + r] * coords[n * 3 + r];
        q[32 + r] = sr; kk[32 + r] = sr;
        qrow[32 + r] = sr; krow[32 + r] = sr;
    }
    float qh[3] = {0.f, 0.f, 0.f}, kh[3] = {0.f, 0.f, 0.f};
    const float* al = alpha + h * 105;
#pragma unroll 5
    for (int d = 0; d < 35; d++) {
        float a0 = al[d * 3 + 0], a1 = al[d * 3 + 1], a2 = al[d * 3 + 2];
        qh[0] += q[d] * a0; qh[1] += q[d] * a1; qh[2] += q[d] * a2;
        kh[0] += kk[d] * a0; kh[1] += kk[d] * a1; kh[2] += kk[d] * a2;
    }
#pragma unroll
    for (int c = 0; c < 3; c++) {
        g_qh[(size_t)(c * 8 + h) * NPTS + n] = qh[c];
        g_kh[(size_t)(c * 8 + h) * NPTS + n] = kh[c];
        float mn = fminf(qh[c], kh[c]);
        float mx = fmaxf(qh[c], kh[c]);
#pragma unroll
        for (int o = 16; o > 0; o >>= 1) {
            mn = fminf(mn, __shfl_xor_sync(0xFFFFFFFFu, mn, o));
            mx = fmaxf(mx, __shfl_xor_sync(0xFFFFFFFFu, mx, o));
        }
        if ((threadIdx.x & 31) == 0) {
            atomicMin(&g_mn[c * 8 + h], encf(mn));
            atomicMax(&g_mx[c * 8 + h], encf(mx));
        }
    }
}

// ---------------- kernel 3: hash shift ----------------
__global__ void k_hs() {
    int t = threadIdx.x;
    if (t < CHN) g_hs[t] = decf(g_mx[t]) - decf(g_mn[t]);
}

// ---------------- kernel 4: build 64-bit sort keys ----------------
__global__ void k_keys(const int* __restrict__ shifts) {
    int t = blockIdx.x * 256 + threadIdx.x;
    int seg = t >> 15;
    int n = t & (NPTS - 1);
    float hsv = g_hs[seg];
    float sh = (float)shifts[t];
    float off = __fmul_rn(sh, hsv);
    g_keys[t] = ((ull)encf(__fadd_rn(g_qh[t], off)) << 32) | (unsigned)n;
    g_keys[(size_t)CHN * NPTS + t] =
        ((ull)encf(__fadd_rn(g_kh[t], off)) << 32) | (unsigned)n;
}

// ---------------- bitonic sort, 8192-element tiles (64KB dynamic smem) ----------------
__global__ void __launch_bounds__(512) k_sort_local8k() {
    extern __shared__ ull s[];
    int chunk = blockIdx.x;                       // 192 chunks; 4 per segment
    size_t base = (size_t)chunk * 8192;
    int isb = (chunk & 3) * 8192;
    for (int p = threadIdx.x; p < 8192; p += 512) s[p] = g_keys[base + p];
    for (int k = 2; k <= 8192; k <<= 1) {
        for (int j = k >> 1; j >= 1; j >>= 1) {
            __syncthreads();
#pragma unroll
            for (int p = 0; p < 8; p++) {
                int t = threadIdx.x + p * 512;
                int i = ((t & ~(j - 1)) << 1) | (t & (j - 1));
                bool up = (((isb + i) & k) == 0);
                ull a = s[i], b = s[i + j];
                if ((a > b) == up) { s[i] = b; s[i + j] = a; }
            }
        }
    }
    __syncthreads();
    for (int p = threadIdx.x; p < 8192; p += 512) g_keys[base + p] = s[p];
}

// single CE step: k=16384, j=8192
__global__ void k_sort_ce_16k() {
    int t = blockIdx.x * 256 + threadIdx.x;       // 48*16384 threads
    int seg = t >> 14;
    int tl = t & 16383;
    int i = ((tl & ~8191) << 1) | (tl & 8191);
    size_t gi = (size_t)seg * NPTS + i;
    bool up = ((i & 16384) == 0);
    ull a = g_keys[gi], b = g_keys[gi + 8192];
    if ((a > b) == up) { g_keys[gi] = b; g_keys[gi + 8192] = a; }
}

// fused double CE step: k=32768 (all ascending), j=16384 then j=8192
__global__ void k_sort_ce2_32k() {
    int t = blockIdx.x * 256 + threadIdx.x;       // 48*8192 threads
    int seg = t >> 13;
    int i = t & 8191;
    size_t gi = (size_t)seg * NPTS + i;
    ull a = g_keys[gi];
    ull b = g_keys[gi + 8192];
    ull c = g_keys[gi + 16384];
    ull d = g_keys[gi + 24576];
    ull tswp;
    if (a > c) { tswp = a; a = c; c = tswp; }     // j=16384
    if (b > d) { tswp = b; b = d; d = tswp; }
    if (a > b) { tswp = a; a = b; b = tswp; }     // j=8192
    if (c > d) { tswp = c; c = d; d = tswp; }
    g_keys[gi] = a; g_keys[gi + 8192] = b;
    g_keys[gi + 16384] = c; g_keys[gi + 24576] = d;
}

__global__ void __launch_bounds__(512) k_sort_merge8k(int k) {
    extern __shared__ ull s[];
    int chunk = blockIdx.x;
    size_t base = (size_t)chunk * 8192;
    int isb = (chunk & 3) * 8192;
    for (int p = threadIdx.x; p < 8192; p += 512) s[p] = g_keys[base + p];
    for (int j = 4096; j >= 1; j >>= 1) {
        __syncthreads();
#pragma unroll
        for (int p = 0; p < 8; p++) {
            int t = threadIdx.x + p * 512;
            int i = ((t & ~(j - 1)) << 1) | (t & (j - 1));
            bool up = (((isb + i) & k) == 0);
            ull a = s[i], b = s[i + j];
            if ((a > b) == up) { s[i] = b; s[i + j] = a; }
        }
    }
    __syncthreads();
    for (int p = threadIdx.x; p < 8192; p += 512) g_keys[base + p] = s[p];
}

// ---------------- kernel 5: bucketed kernelized attention (f32x2 packed) ----------------
__global__ void __launch_bounds__(128) k_attn() {
    __shared__ float ksT[36][128];        // transposed K-hat; row 35 zero
    __shared__ float vsm[128][32];
    __shared__ ull ksq2[64];              // -0.5*|k|^2, as pairs
    int seg = blockIdx.y, b = blockIdx.x, i = threadIdx.x;
    int h = seg & 7;

    unsigned kidx = (unsigned)g_keys[((size_t)(CHN + seg)) * NPTS + b * BSZ + i];
    float tmp[36];
    const float4* kr = (const float4*)(g_khat + ((size_t)h * NPTS + kidx) * QSTR);
#pragma unroll
    for (int u = 0; u < 9; u++) ((float4*)tmp)[u] = kr[u];
    tmp[35] = 0.f;
    float s2 = 0.f;
#pragma unroll
    for (int d = 0; d < 35; d++) s2 += tmp[d] * tmp[d];
    ((float*)ksq2)[i] = -0.5f * s2;
#pragma unroll
    for (int d = 0; d < 36; d++) ksT[d][i] = tmp[d];
    const float4* vr = (const float4*)(g_v + ((size_t)h * NPTS + kidx) * DH);
#pragma unroll
    for (int u = 0; u < 8; u++) ((float4*)&vsm[i][0])[u] = vr[u];

    unsigned qidx = (unsigned)g_keys[(size_t)seg * NPTS + b * BSZ + i];
    float q[36];
    const float4* qr = (const float4*)(g_qhat + ((size_t)h * NPTS + qidx) * QSTR);
#pragma unroll
    for (int u = 0; u < 9; u++) ((float4*)q)[u] = qr[u];
    q[35] = 0.f;
    float qs2 = 0.f;
#pragma unroll
    for (int d = 0; d < 35; d++) qs2 += q[d] * q[d];
    ull qsq2 = pk2(-0.5f * qs2, -0.5f * qs2);
    ull q2[36];
#pragma unroll
    for (int d = 0; d < 36; d++) q2[d] = pk2(q[d], q[d]);

    ull acc2[16];
#pragma unroll
    for (int p = 0; p < 16; p++) acc2[p] = 0ull;
    ull den2 = 0ull;
    __syncthreads();

    for (int j = 0; j < BSZ; j += 4) {
        // dot products for 4 keys (2 pairs), packed over j
        ull sA0 = 0ull, sA1 = 0ull, sB0 = 0ull, sB1 = 0ull;
#pragma unroll
        for (int d = 0; d < 36; d += 2) {
            float4 c0 = *(const float4*)&ksT[d][j];
            float4 c1 = *(const float4*)&ksT[d + 1][j];
            sA0 = f2fma(q2[d], lo2(c0), sA0);
            sB0 = f2fma(q2[d], hi2(c0), sB0);
            sA1 = f2fma(q2[d + 1], lo2(c1), sA1);
            sB1 = f2fma(q2[d + 1], hi2(c1), sB1);
        }
        ull sA = f2add(f2add(sA0, sA1), f2add(ksq2[j >> 1], qsq2));
        ull sB = f2add(f2add(sB0, sB1), f2add(ksq2[(j >> 1) + 1], qsq2));
        float e0, e1, e2, e3;
        fexp2p(sA, e0, e1);
        fexp2p(sB, e2, e3);
        den2 = f2add(den2, pk2(e0 + e2, e1 + e3));
        ull e0d = pk2(e0, e0), e1d = pk2(e1, e1);
        ull e2d = pk2(e2, e2), e3d = pk2(e3, e3);
        const float4* v0 = (const float4*)&vsm[j][0];
        const float4* v1 = (const float4*)&vsm[j + 1][0];
        const float4* v2 = (const float4*)&vsm[j + 2][0];
        const float4* v3 = (const float4*)&vsm[j + 3][0];
#pragma unroll
        for (int p = 0; p < 8; p++) {
            float4 r0 = v0[p], r1 = v1[p], r2 = v2[p], r3 = v3[p];
            acc2[2 * p] = f2fma(e0d, lo2(r0), acc2[2 * p]);
            acc2[2 * p + 1] = f2fma(e0d, hi2(r0), acc2[2 * p + 1]);
            acc2[2 * p] = f2fma(e1d, lo2(r1), acc2[2 * p]);
            acc2[2 * p + 1] = f2fma(e1d, hi2(r1), acc2[2 * p + 1]);
            acc2[2 * p] = f2fma(e2d, lo2(r2), acc2[2 * p]);
            acc2[2 * p + 1] = f2fma(e2d, hi2(r2), acc2[2 * p + 1]);
            acc2[2 * p] = f2fma(e3d, lo2(r3), acc2[2 * p]);
            acc2[2 * p + 1] = f2fma(e3d, hi2(r3), acc2[2 * p + 1]);
        }
    }
    float* od = g_oscr + ((size_t)seg * NPTS + qidx) * DH;
#pragma unroll
    for (int p = 0; p < 8; p++) {
        float o0, o1, o2, o3;
        upk(acc2[2 * p], o0, o1);
        upk(acc2[2 * p + 1], o2, o3);
        ((float4*)od)[p] = make_float4(o0, o1, o2, o3);
    }
    float dl, dh;
    upk(den2, dl, dh);
    g_dscr[(size_t)seg * NPTS + qidx] = dl + dh;
}

// ---------------- kernel 6: combine over hashes + normalize ----------------
__global__ void k_combine() {
    int t = blockIdx.x * 256 + threadIdx.x;
    int p = t & 7;
    int n = (t >> 3) & (NPTS - 1);
    int h = t >> 18;
    float den = g_dscr[(size_t)(0 + h) * NPTS + n] +
                g_dscr[(size_t)(8 + h) * NPTS + n] +
                g_dscr[(size_t)(16 + h) * NPTS + n] + 3e-20f;
    float4 a = ((const float4*)(g_oscr + ((size_t)(0 + h) * NPTS + n) * DH))[p];
    float4 b4 = ((const float4*)(g_oscr + ((size_t)(8 + h) * NPTS + n) * DH))[p];
    float4 c4 = ((const float4*)(g_oscr + ((size_t)(16 + h) * NPTS + n) * DH))[p];
    float inv = 1.0f / den;
    float4 o;
    o.x = (a.x + b4.x + c4.x) * inv;
    o.y = (a.y + b4.y + c4.y) * inv;
    o.z = (a.z + b4.z + c4.z) * inv;
    o.w = (a.w + b4.w + c4.w) * inv;
    ((float4*)(g_attn + (size_t)n * 256 + h * 32))[p] = o;
}

// ---------------- kernel 7: out-proj + residual + LN2 + FF(silu) + residual ----------------
__global__ void __launch_bounds__(128) k_epilogue(
    const float* __restrict__ x, const float* __restrict__ ow,
    const float* __restrict__ ob, const float* __restrict__ n2w,
    const float* __restrict__ n2b, const float* __restrict__ f1w,
    const float* __restrict__ f1b, const float* __restrict__ f2w,
    const float* __restrict__ f2b, float* __restrict__ out) {
    __shared__ float ws[256 * 32];
    __shared__ float f1sT[32 * 32];   // transposed: [jj][d]
    __shared__ float f2s[32 * 32];
    __shared__ float cs[32 * 5];
    int tid = threadIdx.x;
    for (int i = tid; i < 8192; i += 128) ws[i] = ow[i];
    for (int i = tid; i < 1024; i += 128) {
        f1sT[(i & 31) * 32 + (i >> 5)] = f1w[i];
        f2s[i] = f2w[i];
    }
    if (tid < 32) {
        cs[tid] = ob[tid]; cs[32 + tid] = n2w[tid]; cs[64 + tid] = n2b[tid];
        cs[96 + tid] = f1b[tid]; cs[128 + tid] = f2b[tid];
    }
    __syncthreads();
    int n = blockIdx.x * 128 + tid;

    ull acc2[16];
#pragma unroll
    for (int p = 0; p < 16; p++) acc2[p] = pk2(cs[2 * p], cs[2 * p + 1]);
    const float4* ar = (const float4*)(g_attn + (size_t)n * 256);
    for (int jb = 0; jb < 64; jb++) {
        float4 a = ar[jb];
        ull ad0 = pk2(a.x, a.x), ad1 = pk2(a.y, a.y);
        ull ad2 = pk2(a.z, a.z), ad3 = pk2(a.w, a.w);
        const float4* w0 = (const float4*)(ws + (jb * 4 + 0) * 32);
        const float4* w1 = (const float4*)(ws + (jb * 4 + 1) * 32);
        const float4* w2 = (const float4*)(ws + (jb * 4 + 2) * 32);
        const float4* w3 = (const float4*)(ws + (jb * 4 + 3) * 32);
#pragma unroll
        for (int p = 0; p < 8; p++) {
            float4 r0 = w0[p], r1 = w1[p], r2 = w2[p], r3 = w3[p];
            acc2[2 * p] = f2fma(ad0, lo2(r0), acc2[2 * p]);
            acc2[2 * p + 1] = f2fma(ad0, hi2(r0), acc2[2 * p + 1]);
            acc2[2 * p] = f2fma(ad1, lo2(r1), acc2[2 * p]);
            acc2[2 * p + 1] = f2fma(ad1, hi2(r1), acc2[2 * p + 1]);
            acc2[2 * p] = f2fma(ad2, lo2(r2), acc2[2 * p]);
            acc2[2 * p + 1] = f2fma(ad2, hi2(r2), acc2[2 * p + 1]);
            acc2[2 * p] = f2fma(ad3, lo2(r3), acc2[2 * p]);
            acc2[2 * p + 1] = f2fma(ad3, hi2(r3), acc2[2 * p + 1]);
        }
    }
    float acc[32];
#pragma unroll
    for (int p = 0; p < 16; p++) upk(acc2[p], acc[2 * p], acc[2 * p + 1]);

    // residual 1
    float x2[32];
    const float4* xr = (const float4*)(x + (size_t)n * 32);
#pragma unroll
    for (int u = 0; u < 8; u++) {
        float4 xv = xr[u];
        x2[4 * u] = xv.x + acc[4 * u];
        x2[4 * u + 1] = xv.y + acc[4 * u + 1];
        x2[4 * u + 2] = xv.z + acc[4 * u + 2];
        x2[4 * u + 3] = xv.w + acc[4 * u + 3];
    }
    // LN2
    float mu = 0.f;
#pragma unroll
    for (int d = 0; d < 32; d++) mu += x2[d];
    mu *= (1.0f / 32.0f);
    float var = 0.f;
#pragma unroll
    for (int d = 0; d < 32; d++) { float dd = x2[d] - mu; var += dd * dd; }
    var *= (1.0f / 32.0f);
    float rs = rsqrtf(var + 1e-5f);
    float xn2[32];
#pragma unroll
    for (int d = 0; d < 32; d++)
        xn2[d] = (x2[d] - mu) * rs * cs[32 + d] + cs[64 + d];
    ull xp[16];
#pragma unroll
    for (int u = 0; u < 16; u++) xp[u] = pk2(xn2[2 * u], xn2[2 * u + 1]);
    // FF1 + silu
    float h1[32];
#pragma unroll 4
    for (int jj = 0; jj < 32; jj++) {
        const float4* fr = (const float4*)(f1sT + jj * 32);
        ull a0 = 0ull, a1 = 0ull;
#pragma unroll
        for (int u = 0; u < 8; u++) {
            float4 v4 = fr[u];
            a0 = f2fma(lo2(v4), xp[2 * u], a0);
            a1 = f2fma(hi2(v4), xp[2 * u + 1], a1);
        }
        float s0, s1;
        upk(f2add(a0, a1), s0, s1);
        float t2 = cs[96 + jj] + s0 + s1;
        h1[jj] = t2 / (1.0f + fexp(-t2));
    }
    // FF2 + residual 2
    ull o2[16];
#pragma unroll
    for (int p = 0; p < 16; p++) o2[p] = pk2(cs[128 + 2 * p], cs[128 + 2 * p + 1]);
#pragma unroll 4
    for (int jj = 0; jj < 32; jj++) {
        ull hd = pk2(h1[jj], h1[jj]);
        const float4* fr = (const float4*)(f2s + jj * 32);
#pragma unroll
        for (int p = 0; p < 8; p++) {
            float4 v4 = fr[p];
            o2[2 * p] = f2fma(hd, lo2(v4), o2[2 * p]);
            o2[2 * p + 1] = f2fma(hd, hi2(v4), o2[2 * p + 1]);
        }
    }
    float o[32];
#pragma unroll
    for (int p = 0; p < 16; p++) upk(o2[p], o[2 * p], o[2 * p + 1]);
    float4* orow = (float4*)(out + (size_t)n * 32);
#pragma unroll
    for (int u = 0; u < 8; u++)
        orow[u] = make_float4(x2[4 * u] + o[4 * u], x2[4 * u + 1] + o[4 * u + 1],
                              x2[4 * u + 2] + o[4 * u + 2], x2[4 * u + 3] + o[4 * u + 3]);
}

// ---------------- launcher ----------------
extern "C" void kernel_launch(void* const* d_in, const int* in_sizes, int n_in,
                              void* d_out, int out_size) {
    const float* x = (const float*)d_in[0];
    const float* coords = (const float*)d_in[1];
    const int* shifts = (const int*)d_in[2];
    const float* n1w = (const float*)d_in[3];
    const float* n1b = (const float*)d_in[4];
    const float* wq = (const float*)d_in[5];
    const float* wk = (const float*)d_in[6];
    const float* wv = (const float*)d_in[7];
    const float* wr = (const float*)d_in[8];
    const float* alpha = (const float*)d_in[9];
    const float* ow = (const float*)d_in[10];
    const float* ob = (const float*)d_in[11];
    const float* n2w = (const float*)d_in[12];
    const float* n2b = (const float*)d_in[13];
    const float* f1w = (const float*)d_in[14];
    const float* f1b = (const float*)d_in[15];
    const float* f2w = (const float*)d_in[16];
    const float* f2b = (const float*)d_in[17];
    float* out = (float*)d_out;

    static bool attr_done = false;
    if (!attr_done) {
        cudaFuncSetAttribute(k_sort_local8k, cudaFuncAttributeMaxDynamicSharedMemorySize, 65536);
        cudaFuncSetAttribute(k_sort_merge8k, cudaFuncAttributeMaxDynamicSharedMemorySize, 65536);
        attr_done = true;
    }

    k_prep<<<1, 32>>>(wr);
    k_ln_qkv<<<NPTS / 128, 768>>>(x, n1w, n1b, wq, wk, wv);
    k_hash<<<dim3(NPTS / 256, NH), 256>>>(coords, alpha);
    k_hs<<<1, 32>>>();
    k_keys<<<(CHN * NPTS) / 256, 256>>>(shifts);

    // bitonic sort: 48 segments x 32768, stable (index packed in low bits)
    k_sort_local8k<<<2 * CHN * NPTS / 8192, 512, 65536>>>();
    k_sort_ce_16k<<<(2 * CHN * NPTS / 2) / 256, 256>>>();
    k_sort_merge8k<<<2 * CHN * NPTS / 8192, 512, 65536>>>(16384);
    k_sort_ce2_32k<<<(2 * CHN * NPTS / 4) / 256, 256>>>();
    k_sort_merge8k<<<2 * CHN * NPTS / 8192, 512, 65536>>>(32768);

    k_attn<<<dim3(NBK, CHN), 128>>>();
    k_combine<<<(NH * NPTS * 8) / 256, 256>>>();
    k_epilogue<<<NPTS / 128, 128>>>(x, ow, ob, n2w, n2b, f1w, f1b, f2w, f2b, out);
}

// round 3
// speedup vs baseline: 1.2106x; 1.0161x over previous
#include <cuda_runtime.h>
#include <cstdint>

#define NPTS 32768
#define DH 32
#define NH 8
#define NC 3
#define BSZ 128
#define NBK 256
#define CHN 24          // NC*NH
#define QSTR 36         // padded row stride for 35-dim hat vectors

typedef unsigned long long ull;

// ---------------- scratch (static device globals; no allocations) ----------------
__device__ float g_qhat[(size_t)NH * NPTS * QSTR];
__device__ float g_khat[(size_t)NH * NPTS * QSTR];
__device__ float g_v[(size_t)NH * NPTS * DH];
__device__ float g_qh[(size_t)CHN * NPTS];
__device__ float g_kh[(size_t)CHN * NPTS];
__device__ ull   g_keys[(size_t)2 * CHN * NPTS];
__device__ unsigned g_mn[CHN], g_mx[CHN];
__device__ float g_sqrtw[NH * 3];
__device__ float g_oscr[(size_t)CHN * NPTS * DH];
__device__ float g_dscr[(size_t)CHN * NPTS];
__device__ float g_attn[(size_t)NPTS * 256];

// ---------------- f32x2 packed helpers ----------------
__device__ __forceinline__ ull pk2(float a, float b) {
    ull r; asm("mov.b64 %0, {%1, %2};" : "=l"(r) : "f"(a), "f"(b)); return r;
}
__device__ __forceinline__ void upk(ull p, float& a, float& b) {
    asm("mov.b64 {%0, %1}, %2;" : "=f"(a), "=f"(b) : "l"(p));
}
__device__ __forceinline__ ull f2fma(ull a, ull b, ull c) {
    ull d; asm("fma.rn.f32x2 %0, %1, %2, %3;" : "=l"(d) : "l"(a), "l"(b), "l"(c)); return d;
}
__device__ __forceinline__ ull f2add(ull a, ull b) {
    ull d; asm("add.rn.f32x2 %0, %1, %2;" : "=l"(d) : "l"(a), "l"(b)); return d;
}
__device__ __forceinline__ ull lo2(float4 v) { return pk2(v.x, v.y); }
__device__ __forceinline__ ull hi2(float4 v) { return pk2(v.z, v.w); }

// ---------------- sort helpers ----------------
__device__ __forceinline__ unsigned encf(float f) {
    unsigned u = __float_as_uint(f);
    return (u & 0x80000000u) ? ~u : (u | 0x80000000u);
}
__device__ __forceinline__ float decf(unsigned u) {
    return (u & 0x80000000u) ? __uint_as_float(u ^ 0x80000000u)
                             : __uint_as_float(~u);
}

// scalar fast exp; clamped, rel err ~1e-7
__device__ __forceinline__ float fexp(float x) {
    x = fminf(fmaxf(x, -87.0f), 87.0f);
    float t = fmaf(x, 1.4426950408889634f, 12582912.0f);
    float j = t - 12582912.0f;
    float f = fmaf(j, -0.693145751953125f, x);
    f = fmaf(j, -1.4286067653301938e-6f, f);
    float p = 1.3888889e-3f;
    p = fmaf(p, f, 8.3333333e-3f);
    p = fmaf(p, f, 4.1666667e-2f);
    p = fmaf(p, f, 1.6666667e-1f);
    p = fmaf(p, f, 0.5f);
    p = fmaf(p, f, 1.0f);
    p = fmaf(p, f, 1.0f);
    return __int_as_float(__float_as_int(p) + (__float_as_int(t) << 23));
}

// packed exp for x <= ~0; underflow-guarded
__device__ __forceinline__ void fexp2p(ull x2, float& e0, float& e1) {
    const ull L2E = pk2(1.4426950408889634f, 1.4426950408889634f);
    const ull MAG = pk2(12582912.0f, 12582912.0f);
    const ull NMAG = pk2(-12582912.0f, -12582912.0f);
    ull t2 = f2fma(x2, L2E, MAG);
    ull j2 = f2add(t2, NMAG);
    ull f2 = f2fma(j2, pk2(-0.693145751953125f, -0.693145751953125f), x2);
    f2 = f2fma(j2, pk2(-1.4286067653301938e-6f, -1.4286067653301938e-6f), f2);
    ull p = pk2(1.3888889e-3f, 1.3888889e-3f);
    p = f2fma(p, f2, pk2(8.3333333e-3f, 8.3333333e-3f));
    p = f2fma(p, f2, pk2(4.1666667e-2f, 4.1666667e-2f));
    p = f2fma(p, f2, pk2(1.6666667e-1f, 1.6666667e-1f));
    p = f2fma(p, f2, pk2(0.5f, 0.5f));
    p = f2fma(p, f2, pk2(1.0f, 1.0f));
    p = f2fma(p, f2, pk2(1.0f, 1.0f));
    float p0, p1, t0, t1;
    upk(p, p0, p1); upk(t2, t0, t1);
    float r0 = __int_as_float(__float_as_int(p0) + (__float_as_int(t0) << 23));
    float r1 = __int_as_float(__float_as_int(p1) + (__float_as_int(t1) << 23));
    e0 = (t0 < 12582792.0f) ? 0.0f : r0;
    e1 = (t1 < 12582792.0f) ? 0.0f : r1;
}

// ---------------- kernel 1: LayerNorm + QKV projection (+prep fold) ----------------
__global__ void __launch_bounds__(768) k_ln_qkv(
    const float* __restrict__ x, const float* __restrict__ n1w,
    const float* __restrict__ n1b, const float* __restrict__ wq,
    const float* __restrict__ wk, const float* __restrict__ wv,
    const float* __restrict__ wr) {
    __shared__ float xs[128 * QSTR];
    int base = blockIdx.x * 128;
    int tid = threadIdx.x;
    if (blockIdx.x == 0 && tid < CHN) {        // folded k_prep
        g_mn[tid] = 0xFFFFFFFFu;
        g_mx[tid] = 0u;
        int h = tid / 3, r = tid % 3;
        float qw = 0.f;
        for (int k = 0; k < 8; k++) {
            float s = 0.f;
            for (int d = 0; d < 32; d++) s += wr[(h * 32 + d) * 24 + r * 8 + k];
            qw += expf(fminf(s, 50.f));
        }
        g_sqrtw[tid] = sqrtf(2.f * qw);
    }
    if (tid < 128) {
        int n = base + tid;
        float r[32];
        const float4* xr = (const float4*)(x + (size_t)n * 32);
#pragma unroll
        for (int u = 0; u < 8; u++) {
            float4 v4 = xr[u];
            r[4 * u] = v4.x; r[4 * u + 1] = v4.y; r[4 * u + 2] = v4.z; r[4 * u + 3] = v4.w;
        }
        float mu = 0.f;
#pragma unroll
        for (int d = 0; d < 32; d++) mu += r[d];
        mu *= (1.0f / 32.0f);
        float var = 0.f;
#pragma unroll
        for (int d = 0; d < 32; d++) { float dd = r[d] - mu; var += dd * dd; }
        var *= (1.0f / 32.0f);
        float rs = rsqrtf(var + 1e-5f);
#pragma unroll
        for (int d = 0; d < 32; d++)
            xs[tid * QSTR + d] = (r[d] - mu) * rs * n1w[d] + n1b[d];
    }
    __syncthreads();
    int j = tid;
    int proj = j >> 8, jj = j & 255;
    const float* W = (proj == 0) ? wq : (proj == 1) ? wk : wv;
    ull wpk[16];
#pragma unroll
    for (int d = 0; d < 16; d++)
        wpk[d] = pk2(W[(2 * d) * 256 + jj], W[(2 * d + 1) * 256 + jj]);
    int h = jj >> 5, d0 = jj & 31;
    float* dst;
    int stride;
    if (proj == 0) { dst = g_qhat; stride = QSTR; }
    else if (proj == 1) { dst = g_khat; stride = QSTR; }
    else { dst = g_v; stride = DH; }
    for (int r = 0; r < 128; r++) {
        const float4* xr = (const float4*)(xs + r * QSTR);
        ull a0 = 0, a1 = 0;
#pragma unroll
        for (int u = 0; u < 8; u++) {
            float4 v4 = xr[u];
            a0 = f2fma(lo2(v4), wpk[2 * u], a0);
            a1 = f2fma(hi2(v4), wpk[2 * u + 1], a1);
        }
        float s0, s1;
        upk(f2add(a0, a1), s0, s1);
        dst[((size_t)h * NPTS + (base + r)) * stride + d0] = s0 + s1;
    }
}

// ---------------- kernel 2: hat tails + LSH hashes + min/max ----------------
__global__ void k_hash(const float* __restrict__ coords, const float* __restrict__ alpha) {
    int h = blockIdx.y;
    int n = blockIdx.x * 256 + threadIdx.x;
    float q[36], kk[36];
    float* qrow = g_qhat + ((size_t)h * NPTS + n) * QSTR;
    float* krow = g_khat + ((size_t)h * NPTS + n) * QSTR;
#pragma unroll
    for (int u = 0; u < 8; u++) {
        ((float4*)q)[u] = ((const float4*)qrow)[u];
        ((float4*)kk)[u] = ((const float4*)krow)[u];
    }
#pragma unroll
    for (int r = 0; r < 3; r++) {
        float sr = g_sqrtw[h * 3 + r] * coords[n * 3 + r];
        q[32 + r] = sr; kk[32 + r] = sr;
        qrow[32 + r] = sr; krow[32 + r] = sr;
    }
    qrow[35] = 0.f; krow[35] = 0.f;               // zero pad element
    float qh[3] = {0.f, 0.f, 0.f}, kh[3] = {0.f, 0.f, 0.f};
    const float* al = alpha + h * 105;
#pragma unroll 5
    for (int d = 0; d < 35; d++) {
        float a0 = al[d * 3 + 0], a1 = al[d * 3 + 1], a2 = al[d * 3 + 2];
        qh[0] += q[d] * a0; qh[1] += q[d] * a1; qh[2] += q[d] * a2;
        kh[0] += kk[d] * a0; kh[1] += kk[d] * a1; kh[2] += kk[d] * a2;
    }
#pragma unroll
    for (int c = 0; c < 3; c++) {
        g_qh[(size_t)(c * 8 + h) * NPTS + n] = qh[c];
        g_kh[(size_t)(c * 8 + h) * NPTS + n] = kh[c];
        float mn = fminf(qh[c], kh[c]);
        float mx = fmaxf(qh[c], kh[c]);
#pragma unroll
        for (int o = 16; o > 0; o >>= 1) {
            mn = fminf(mn, __shfl_xor_sync(0xFFFFFFFFu, mn, o));
            mx = fmaxf(mx, __shfl_xor_sync(0xFFFFFFFFu, mx, o));
        }
        if ((threadIdx.x & 31) == 0) {
            atomicMin(&g_mn[c * 8 + h], encf(mn));
            atomicMax(&g_mx[c * 8 + h], encf(mx));
        }
    }
}

// ---------------- kernel 4: build 64-bit sort keys (+hs fold) ----------------
__global__ void k_keys(const int* __restrict__ shifts) {
    int t = blockIdx.x * 256 + threadIdx.x;
    int seg = t >> 15;
    int n = t & (NPTS - 1);
    float hsv = decf(g_mx[seg]) - decf(g_mn[seg]);
    float sh = (float)shifts[t];
    float off = __fmul_rn(sh, hsv);
    g_keys[t] = ((ull)encf(__fadd_rn(g_qh[t], off)) << 32) | (unsigned)n;
    g_keys[(size_t)CHN * NPTS + t] =
        ((ull)encf(__fadd_rn(g_kh[t], off)) << 32) | (unsigned)n;
}

// ---------------- hybrid bitonic sort primitives ----------------
// 512 threads, 16 elems/thread; element index i(s) = w*512 + s*32 + l.
template<int J>
__device__ __forceinline__ void shflp(ull* r, int ibase, int isb, int l, int k_) {
#pragma unroll
    for (int s = 0; s < 16; s++) {
        int i = ibase + s * 32;
        bool up = (((isb + i) & k_) == 0);
        ull o = __shfl_xor_sync(0xFFFFFFFFu, r[s], J);
        bool kmin = (((l & J) == 0) == up);
        ull lo_ = (r[s] < o) ? r[s] : o;
        ull hi_ = (r[s] < o) ? o : r[s];
        r[s] = kmin ? lo_ : hi_;
    }
}
template<int J>
__device__ __forceinline__ void slotp(ull* r, int ibase, int isb, int k_) {
    constexpr int js = J >> 5;
#pragma unroll
    for (int s = 0; s < 16; s++) {
        if (!(s & js)) {
            int sp = s | js;
            int i = ibase + s * 32;
            bool up = (((isb + i) & k_) == 0);
            if ((r[s] > r[sp]) == up) { ull t2 = r[s]; r[s] = r[sp]; r[sp] = t2; }
        }
    }
}
// all passes with J <= min(k/2, 256), descending
__device__ __forceinline__ void regpasses(ull* r, int ibase, int isb, int l, int k_) {
    int half = k_ >> 1;
    if (half >= 256) slotp<256>(r, ibase, isb, k_);
    if (half >= 128) slotp<128>(r, ibase, isb, k_);
    if (half >= 64)  slotp<64>(r, ibase, isb, k_);
    if (half >= 32)  slotp<32>(r, ibase, isb, k_);
    if (half >= 16)  shflp<16>(r, ibase, isb, l, k_);
    if (half >= 8)   shflp<8>(r, ibase, isb, l, k_);
    if (half >= 4)   shflp<4>(r, ibase, isb, l, k_);
    if (half >= 2)   shflp<2>(r, ibase, isb, l, k_);
    shflp<1>(r, ibase, isb, l, k_);
}
__device__ __forceinline__ void smem_pass(ull* s, int isb, int k_, int j_, int tid) {
#pragma unroll
    for (int p = 0; p < 8; p++) {
        int t = tid + p * 512;
        int i = ((t & ~(j_ - 1)) << 1) | (t & (j_ - 1));
        bool up = (((isb + i) & k_) == 0);
        ull a = s[i], b = s[i + j_];
        if ((a > b) == up) { s[i] = b; s[i + j_] = a; }
    }
}

__global__ void __launch_bounds__(512) k_sort_local8k() {
    extern __shared__ ull s[];
    int chunk = blockIdx.x;
    size_t base = (size_t)chunk * 8192;
    int isb = (chunk & 3) * 8192;
    int tid = threadIdx.x;
    int w = tid >> 5, l = tid & 31;
    int ibase = w * 512 + l;
    ull r[16];
#pragma unroll
    for (int s_ = 0; s_ < 16; s_++) r[s_] = g_keys[base + ibase + s_ * 32];

    for (int k_ = 2; k_ <= 512; k_ <<= 1) regpasses(r, ibase, isb, l, k_);

    for (int k_ = 1024; k_ <= 8192; k_ <<= 1) {
#pragma unroll
        for (int s_ = 0; s_ < 16; s_++) s[ibase + s_ * 32] = r[s_];
        __syncthreads();
        for (int j_ = k_ >> 1; j_ >= 512; j_ >>= 1) {
            smem_pass(s, isb, k_, j_, tid);
            __syncthreads();
        }
#pragma unroll
        for (int s_ = 0; s_ < 16; s_++) r[s_] = s[ibase + s_ * 32];
        __syncthreads();
        regpasses(r, ibase, isb, l, k_);
    }
#pragma unroll
    for (int s_ = 0; s_ < 16; s_++) g_keys[base + ibase + s_ * 32] = r[s_];
}

// single CE step: k=16384, j=8192
__global__ void k_sort_ce_16k() {
    int t = blockIdx.x * 256 + threadIdx.x;
    int seg = t >> 14;
    int tl = t & 16383;
    int i = ((tl & ~8191) << 1) | (tl & 8191);
    size_t gi = (size_t)seg * NPTS + i;
    bool up = ((i & 16384) == 0);
    ull a = g_keys[gi], b = g_keys[gi + 8192];
    if ((a > b) == up) { g_keys[gi] = b; g_keys[gi + 8192] = a; }
}

// fused double CE step: k=32768 (all ascending), j=16384 then j=8192
__global__ void k_sort_ce2_32k() {
    int t = blockIdx.x * 256 + threadIdx.x;
    int seg = t >> 13;
    int i = t & 8191;
    size_t gi = (size_t)seg * NPTS + i;
    ull a = g_keys[gi];
    ull b = g_keys[gi + 8192];
    ull c = g_keys[gi + 16384];
    ull d = g_keys[gi + 24576];
    ull tswp;
    if (a > c) { tswp = a; a = c; c = tswp; }
    if (b > d) { tswp = b; b = d; d = tswp; }
    if (a > b) { tswp = a; a = b; b = tswp; }
    if (c > d) { tswp = c; c = d; d = tswp; }
    g_keys[gi] = a; g_keys[gi + 8192] = b;
    g_keys[gi + 16384] = c; g_keys[gi + 24576] = d;
}

__global__ void __launch_bounds__(512) k_sort_merge8k(int kglob) {
    extern __shared__ ull s[];
    int chunk = blockIdx.x;
    size_t base = (size_t)chunk * 8192;
    int isb = (chunk & 3) * 8192;
    int tid = threadIdx.x;
    int w = tid >> 5, l = tid & 31;
    int ibase = w * 512 + l;
#pragma unroll
    for (int p = 0; p < 16; p++) s[tid + p * 512] = g_keys[base + tid + p * 512];
    __syncthreads();
    for (int j_ = 4096; j_ >= 512; j_ >>= 1) {
        smem_pass(s, isb, kglob, j_, tid);
        __syncthreads();
    }
    ull r[16];
#pragma unroll
    for (int s_ = 0; s_ < 16; s_++) r[s_] = s[ibase + s_ * 32];
    regpasses(r, ibase, isb, l, kglob);
#pragma unroll
    for (int s_ = 0; s_ < 16; s_++) g_keys[base + ibase + s_ * 32] = r[s_];
}

// ---------------- kernel 5: bucketed attention (2 buckets/block, 2 q/thread) ----------------
// smem: ks 2*128*36, vs 2*128*32, ksq 2*128  (70656 B dynamic)
__global__ void __launch_bounds__(128) k_attn() {
    extern __shared__ float sm[];
    float* ks = sm;                    // [2][128][36]
    float* vs = sm + 9216;             // [2][128][32]
    float* ksq = sm + 9216 + 8192;     // [2][128]
    int seg = blockIdx.y;
    int h = seg & 7;
    int t = threadIdx.x;
    int tb = t >> 6, tq = t & 63;
    int bucket = blockIdx.x * 2 + tb;

    const ull* kkey = g_keys + ((size_t)(CHN + seg)) * NPTS + bucket * BSZ;
    const ull* qkey = g_keys + (size_t)seg * NPTS + bucket * BSZ;

    // load 2 K rows + 2 V rows per thread
#pragma unroll
    for (int rr = 0; rr < 2; rr++) {
        int row = tq + rr * 64;
        unsigned kidx = (unsigned)kkey[row];
        const float4* kr = (const float4*)(g_khat + ((size_t)h * NPTS + kidx) * QSTR);
        float tmp[36];
#pragma unroll
        for (int u = 0; u < 9; u++) ((float4*)tmp)[u] = kr[u];
        float s2 = 0.f;
#pragma unroll
        for (int d = 0; d < 35; d++) s2 += tmp[d] * tmp[d];
        ksq[tb * 128 + row] = -0.5f * s2;
        float* kd = ks + (tb * 128 + row) * 36;
#pragma unroll
        for (int u = 0; u < 9; u++) ((float4*)kd)[u] = ((float4*)tmp)[u];
        const float4* vr = (const float4*)(g_v + ((size_t)h * NPTS + kidx) * DH);
        float* vd = vs + (tb * 128 + row) * 32;
#pragma unroll
        for (int u = 0; u < 8; u++) ((float4*)vd)[u] = vr[u];
    }

    // load 2 Q rows into registers (packed over d)
    unsigned qidxA = (unsigned)qkey[tq];
    unsigned qidxB = (unsigned)qkey[tq + 64];
    ull qAp[18], qBp[18];
    {
        const float4* qr = (const float4*)(g_qhat + ((size_t)h * NPTS + qidxA) * QSTR);
#pragma unroll
        for (int u = 0; u < 9; u++) ((float4*)qAp)[u] = qr[u];
        const float4* qr2 = (const float4*)(g_qhat + ((size_t)h * NPTS + qidxB) * QSTR);
#pragma unroll
        for (int u = 0; u < 9; u++) ((float4*)qBp)[u] = qr2[u];
    }
    float qsqA = 0.f, qsqB = 0.f;
#pragma unroll
    for (int d = 0; d < 35; d++) {
        qsqA += ((float*)qAp)[d] * ((float*)qAp)[d];
        qsqB += ((float*)qBp)[d] * ((float*)qBp)[d];
    }
    qsqA *= -0.5f; qsqB *= -0.5f;

    ull accA[16], accB[16];
#pragma unroll
    for (int p = 0; p < 16; p++) { accA[p] = 0ull; accB[p] = 0ull; }
    float denA = 0.f, denB = 0.f;
    __syncthreads();

    const float* ksb = ks + tb * 128 * 36;
    const float* vsb = vs + tb * 128 * 32;
    const float* ksqb = ksq + tb * 128;
    for (int j = 0; j < BSZ; j++) {
        ull c[18];
        const float4* krow = (const float4*)(ksb + j * 36);
#pragma unroll
        for (int u = 0; u < 9; u++) ((float4*)c)[u] = krow[u];
        ull dA0 = 0ull, dA1 = 0ull, dB0 = 0ull, dB1 = 0ull;
#pragma unroll
        for (int p = 0; p < 18; p += 2) {
            dA0 = f2fma(qAp[p], c[p], dA0);
            dA1 = f2fma(qAp[p + 1], c[p + 1], dA1);
            dB0 = f2fma(qBp[p], c[p], dB0);
            dB1 = f2fma(qBp[p + 1], c[p + 1], dB1);
        }
        float ksqv = ksqb[j];
        float a0, a1, b0, b1;
        upk(f2add(dA0, dA1), a0, a1);
        upk(f2add(dB0, dB1), b0, b1);
        float sA = a0 + a1 + qsqA + ksqv;
        float sB = b0 + b1 + qsqB + ksqv;
        float eA, eB;
        fexp2p(pk2(sA, sB), eA, eB);
        denA += eA; denB += eB;
        ull eAd = pk2(eA, eA), eBd = pk2(eB, eB);
        ull vp[16];
        const float4* vrow = (const float4*)(vsb + j * 32);
#pragma unroll
        for (int u = 0; u < 8; u++) ((float4*)vp)[u] = vrow[u];
#pragma unroll
        for (int p = 0; p < 16; p++) {
            accA[p] = f2fma(eAd, vp[p], accA[p]);
            accB[p] = f2fma(eBd, vp[p], accB[p]);
        }
    }
    float* odA = g_oscr + ((size_t)seg * NPTS + qidxA) * DH;
    float* odB = g_oscr + ((size_t)seg * NPTS + qidxB) * DH;
#pragma unroll
    for (int p = 0; p < 8; p++) {
        float o0, o1, o2, o3;
        upk(accA[2 * p], o0, o1); upk(accA[2 * p + 1], o2, o3);
        ((float4*)odA)[p] = make_float4(o0, o1, o2, o3);
    }
#pragma unroll
    for (int p = 0; p < 8; p++) {
        float o0, o1, o2, o3;
        upk(accB[2 * p], o0, o1); upk(accB[2 * p + 1], o2, o3);
        ((float4*)odB)[p] = make_float4(o0, o1, o2, o3);
    }
    g_dscr[(size_t)seg * NPTS + qidxA] = denA;
    g_dscr[(size_t)seg * NPTS + qidxB] = denB;
}

// ---------------- kernel 6: combine over hashes + normalize ----------------
__global__ void k_combine() {
    int t = blockIdx.x * 256 + threadIdx.x;
    int p = t & 7;
    int n = (t >> 3) & (NPTS - 1);
    int h = t >> 18;
    float den = g_dscr[(size_t)(0 + h) * NPTS + n] +
                g_dscr[(size_t)(8 + h) * NPTS + n] +
                g_dscr[(size_t)(16 + h) * NPTS + n] + 3e-20f;
    float4 a = ((const float4*)(g_oscr + ((size_t)(0 + h) * NPTS + n) * DH))[p];
    float4 b4 = ((const float4*)(g_oscr + ((size_t)(8 + h) * NPTS + n) * DH))[p];
    float4 c4 = ((const float4*)(g_oscr + ((size_t)(16 + h) * NPTS + n) * DH))[p];
    float inv = 1.0f / den;
    float4 o;
    o.x = (a.x + b4.x + c4.x) * inv;
    o.y = (a.y + b4.y + c4.y) * inv;
    o.z = (a.z + b4.z + c4.z) * inv;
    o.w = (a.w + b4.w + c4.w) * inv;
    ((float4*)(g_attn + (size_t)n * 256 + h * 32))[p] = o;
}

// ---------------- kernel 7: out-proj + residual + LN2 + FF(silu) + residual ----------------
__global__ void __launch_bounds__(128) k_epilogue(
    const float* __restrict__ x, const float* __restrict__ ow,
    const float* __restrict__ ob, const float* __restrict__ n2w,
    const float* __restrict__ n2b, const float* __restrict__ f1w,
    const float* __restrict__ f1b, const float* __restrict__ f2w,
    const float* __restrict__ f2b, float* __restrict__ out) {
    __shared__ float ws[256 * 32];
    __shared__ float f1sT[32 * 32];
    __shared__ float f2s[32 * 32];
    __shared__ float cs[32 * 5];
    int tid = threadIdx.x;
    for (int i = tid; i < 8192; i += 128) ws[i] = ow[i];
    for (int i = tid; i < 1024; i += 128) {
        f1sT[(i & 31) * 32 + (i >> 5)] = f1w[i];
        f2s[i] = f2w[i];
    }
    if (tid < 32) {
        cs[tid] = ob[tid]; cs[32 + tid] = n2w[tid]; cs[64 + tid] = n2b[tid];
        cs[96 + tid] = f1b[tid]; cs[128 + tid] = f2b[tid];
    }
    __syncthreads();
    int n = blockIdx.x * 128 + tid;

    ull acc2[16];
#pragma unroll
    for (int p = 0; p < 16; p++) acc2[p] = pk2(cs[2 * p], cs[2 * p + 1]);
    const float4* ar = (const float4*)(g_attn + (size_t)n * 256);
    for (int jb = 0; jb < 64; jb++) {
        float4 a = ar[jb];
        ull ad0 = pk2(a.x, a.x), ad1 = pk2(a.y, a.y);
        ull ad2 = pk2(a.z, a.z), ad3 = pk2(a.w, a.w);
        const float4* w0 = (const float4*)(ws + (jb * 4 + 0) * 32);
        const float4* w1 = (const float4*)(ws + (jb * 4 + 1) * 32);
        const float4* w2 = (const float4*)(ws + (jb * 4 + 2) * 32);
        const float4* w3 = (const float4*)(ws + (jb * 4 + 3) * 32);
#pragma unroll
        for (int p = 0; p < 8; p++) {
            float4 r0 = w0[p], r1 = w1[p], r2 = w2[p], r3 = w3[p];
            acc2[2 * p] = f2fma(ad0, lo2(r0), acc2[2 * p]);
            acc2[2 * p + 1] = f2fma(ad0, hi2(r0), acc2[2 * p + 1]);
            acc2[2 * p] = f2fma(ad1, lo2(r1), acc2[2 * p]);
            acc2[2 * p + 1] = f2fma(ad1, hi2(r1), acc2[2 * p + 1]);
            acc2[2 * p] = f2fma(ad2, lo2(r2), acc2[2 * p]);
            acc2[2 * p + 1] = f2fma(ad2, hi2(r2), acc2[2 * p + 1]);
            acc2[2 * p] = f2fma(ad3, lo2(r3), acc2[2 * p]);
            acc2[2 * p + 1] = f2fma(ad3, hi2(r3), acc2[2 * p + 1]);
        }
    }
    float acc[32];
#pragma unroll
    for (int p = 0; p < 16; p++) upk(acc2[p], acc[2 * p], acc[2 * p + 1]);

    float x2[32];
    const float4* xr = (const float4*)(x + (size_t)n * 32);
#pragma unroll
    for (int u = 0; u < 8; u++) {
        float4 xv = xr[u];
        x2[4 * u] = xv.x + acc[4 * u];
        x2[4 * u + 1] = xv.y + acc[4 * u + 1];
        x2[4 * u + 2] = xv.z + acc[4 * u + 2];
        x2[4 * u + 3] = xv.w + acc[4 * u + 3];
    }
    float mu = 0.f;
#pragma unroll
    for (int d = 0; d < 32; d++) mu += x2[d];
    mu *= (1.0f / 32.0f);
    float var = 0.f;
#pragma unroll
    for (int d = 0; d < 32; d++) { float dd = x2[d] - mu; var += dd * dd; }
    var *= (1.0f / 32.0f);
    float rs = rsqrtf(var + 1e-5f);
    float xn2[32];
#pragma unroll
    for (int d = 0; d < 32; d++)
        xn2[d] = (x2[d] - mu) * rs * cs[32 + d] + cs[64 + d];
    ull xp[16];
#pragma unroll
    for (int u = 0; u < 16; u++) xp[u] = pk2(xn2[2 * u], xn2[2 * u + 1]);
    float h1[32];
#pragma unroll 4
    for (int jj = 0; jj < 32; jj++) {
        const float4* fr = (const float4*)(f1sT + jj * 32);
        ull a0 = 0ull, a1 = 0ull;
#pragma unroll
        for (int u = 0; u < 8; u++) {
            float4 v4 = fr[u];
            a0 = f2fma(lo2(v4), xp[2 * u], a0);
            a1 = f2fma(hi2(v4), xp[2 * u + 1], a1);
        }
        float s0, s1;
        upk(f2add(a0, a1), s0, s1);
        float t2 = cs[96 + jj] + s0 + s1;
        h1[jj] = t2 / (1.0f + fexp(-t2));
    }
    ull o2[16];
#pragma unroll
    for (int p = 0; p < 16; p++) o2[p] = pk2(cs[128 + 2 * p], cs[128 + 2 * p + 1]);
#pragma unroll 4
    for (int jj = 0; jj < 32; jj++) {
        ull hd = pk2(h1[jj], h1[jj]);
        const float4* fr = (const float4*)(f2s + jj * 32);
#pragma unroll
        for (int p = 0; p < 8; p++) {
            float4 v4 = fr[p];
            o2[2 * p] = f2fma(hd, lo2(v4), o2[2 * p]);
            o2[2 * p + 1] = f2fma(hd, hi2(v4), o2[2 * p + 1]);
        }
    }
    float o[32];
#pragma unroll
    for (int p = 0; p < 16; p++) upk(o2[p], o[2 * p], o[2 * p + 1]);
    float4* orow = (float4*)(out + (size_t)n * 32);
#pragma unroll
    for (int u = 0; u < 8; u++)
        orow[u] = make_float4(x2[4 * u] + o[4 * u], x2[4 * u + 1] + o[4 * u + 1],
                              x2[4 * u + 2] + o[4 * u + 2], x2[4 * u + 3] + o[4 * u + 3]);
}

// ---------------- launcher ----------------
extern "C" void kernel_launch(void* const* d_in, const int* in_sizes, int n_in,
                              void* d_out, int out_size) {
    const float* x = (const float*)d_in[0];
    const float* coords = (const float*)d_in[1];
    const int* shifts = (const int*)d_in[2];
    const float* n1w = (const float*)d_in[3];
    const float* n1b = (const float*)d_in[4];
    const float* wq = (const float*)d_in[5];
    const float* wk = (const float*)d_in[6];
    const float* wv = (const float*)d_in[7];
    const float* wr = (const float*)d_in[8];
    const float* alpha = (const float*)d_in[9];
    const float* ow = (const float*)d_in[10];
    const float* ob = (const float*)d_in[11];
    const float* n2w = (const float*)d_in[12];
    const float* n2b = (const float*)d_in[13];
    const float* f1w = (const float*)d_in[14];
    const float* f1b = (const float*)d_in[15];
    const float* f2w = (const float*)d_in[16];
    const float* f2b = (const float*)d_in[17];
    float* out = (float*)d_out;

    cudaFuncSetAttribute(k_sort_local8k, cudaFuncAttributeMaxDynamicSharedMemorySize, 65536);
    cudaFuncSetAttribute(k_sort_merge8k, cudaFuncAttributeMaxDynamicSharedMemorySize, 65536);
    cudaFuncSetAttribute(k_attn, cudaFuncAttributeMaxDynamicSharedMemorySize, 71680);

    k_ln_qkv<<<NPTS / 128, 768>>>(x, n1w, n1b, wq, wk, wv, wr);
    k_hash<<<dim3(NPTS / 256, NH), 256>>>(coords, alpha);
    k_keys<<<(CHN * NPTS) / 256, 256>>>(shifts);

    k_sort_local8k<<<2 * CHN * NPTS / 8192, 512, 65536>>>();
    k_sort_ce_16k<<<(2 * CHN * NPTS / 2) / 256, 256>>>();
    k_sort_merge8k<<<2 * CHN * NPTS / 8192, 512, 65536>>>(16384);
    k_sort_ce2_32k<<<(2 * CHN * NPTS / 4) / 256, 256>>>();
    k_sort_merge8k<<<2 * CHN * NPTS / 8192, 512, 65536>>>(32768);

    k_attn<<<dim3(NBK / 2, CHN), 128, 71680>>>();
    k_combine<<<(NH * NPTS * 8) / 256, 256>>>();
    k_epilogue<<<NPTS / 128, 128>>>(x, ow, ob, n2w, n2b, f1w, f1b, f2w, f2b, out);
}

// round 4
// speedup vs baseline: 1.2437x; 1.0273x over previous
#include <cuda_runtime.h>
#include <cstdint>

#define NPTS 32768
#define DH 32
#define NH 8
#define NC 3
#define BSZ 128
#define NBK 256
#define CHN 24          // NC*NH
#define QSTR 36         // padded row stride for 35-dim hat vectors

typedef unsigned long long ull;

// ---------------- scratch (static device globals; no allocations) ----------------
__device__ float g_qhat[(size_t)NH * NPTS * QSTR];
__device__ float g_khat[(size_t)NH * NPTS * QSTR];
__device__ float g_v[(size_t)NH * NPTS * DH];
__device__ float g_qh[(size_t)CHN * NPTS];
__device__ float g_kh[(size_t)CHN * NPTS];
__device__ ull   g_keys[(size_t)2 * CHN * NPTS];
__device__ ull   g_keys2[(size_t)2 * CHN * NPTS];
__device__ unsigned g_mn[CHN], g_mx[CHN];
__device__ float g_sqrtw[NH * 3];
__device__ float g_oscr[(size_t)CHN * NPTS * DH];
__device__ float g_dscr[(size_t)CHN * NPTS];
__device__ float g_attn[(size_t)NPTS * 256];

// ---------------- f32x2 packed helpers ----------------
__device__ __forceinline__ ull pk2(float a, float b) {
    ull r; asm("mov.b64 %0, {%1, %2};" : "=l"(r) : "f"(a), "f"(b)); return r;
}
__device__ __forceinline__ void upk(ull p, float& a, float& b) {
    asm("mov.b64 {%0, %1}, %2;" : "=f"(a), "=f"(b) : "l"(p));
}
__device__ __forceinline__ ull f2fma(ull a, ull b, ull c) {
    ull d; asm("fma.rn.f32x2 %0, %1, %2, %3;" : "=l"(d) : "l"(a), "l"(b), "l"(c)); return d;
}
__device__ __forceinline__ ull f2add(ull a, ull b) {
    ull d; asm("add.rn.f32x2 %0, %1, %2;" : "=l"(d) : "l"(a), "l"(b)); return d;
}
__device__ __forceinline__ ull lo2(float4 v) { return pk2(v.x, v.y); }
__device__ __forceinline__ ull hi2(float4 v) { return pk2(v.z, v.w); }

// ---------------- sort helpers ----------------
__device__ __forceinline__ unsigned encf(float f) {
    unsigned u = __float_as_uint(f);
    return (u & 0x80000000u) ? ~u : (u | 0x80000000u);
}
__device__ __forceinline__ float decf(unsigned u) {
    return (u & 0x80000000u) ? __uint_as_float(u ^ 0x80000000u)
                             : __uint_as_float(~u);
}

// scalar fast exp; clamped, rel err ~1e-7
__device__ __forceinline__ float fexp(float x) {
    x = fminf(fmaxf(x, -87.0f), 87.0f);
    float t = fmaf(x, 1.4426950408889634f, 12582912.0f);
    float j = t - 12582912.0f;
    float f = fmaf(j, -0.693145751953125f, x);
    f = fmaf(j, -1.4286067653301938e-6f, f);
    float p = 1.3888889e-3f;
    p = fmaf(p, f, 8.3333333e-3f);
    p = fmaf(p, f, 4.1666667e-2f);
    p = fmaf(p, f, 1.6666667e-1f);
    p = fmaf(p, f, 0.5f);
    p = fmaf(p, f, 1.0f);
    p = fmaf(p, f, 1.0f);
    return __int_as_float(__float_as_int(p) + (__float_as_int(t) << 23));
}

// packed exp for x <= ~0; underflow-guarded
__device__ __forceinline__ void fexp2p(ull x2, float& e0, float& e1) {
    const ull L2E = pk2(1.4426950408889634f, 1.4426950408889634f);
    const ull MAG = pk2(12582912.0f, 12582912.0f);
    const ull NMAG = pk2(-12582912.0f, -12582912.0f);
    ull t2 = f2fma(x2, L2E, MAG);
    ull j2 = f2add(t2, NMAG);
    ull f2 = f2fma(j2, pk2(-0.693145751953125f, -0.693145751953125f), x2);
    f2 = f2fma(j2, pk2(-1.4286067653301938e-6f, -1.4286067653301938e-6f), f2);
    ull p = pk2(1.3888889e-3f, 1.3888889e-3f);
    p = f2fma(p, f2, pk2(8.3333333e-3f, 8.3333333e-3f));
    p = f2fma(p, f2, pk2(4.1666667e-2f, 4.1666667e-2f));
    p = f2fma(p, f2, pk2(1.6666667e-1f, 1.6666667e-1f));
    p = f2fma(p, f2, pk2(0.5f, 0.5f));
    p = f2fma(p, f2, pk2(1.0f, 1.0f));
    p = f2fma(p, f2, pk2(1.0f, 1.0f));
    float p0, p1, t0, t1;
    upk(p, p0, p1); upk(t2, t0, t1);
    float r0 = __int_as_float(__float_as_int(p0) + (__float_as_int(t0) << 23));
    float r1 = __int_as_float(__float_as_int(p1) + (__float_as_int(t1) << 23));
    e0 = (t0 < 12582792.0f) ? 0.0f : r0;
    e1 = (t1 < 12582792.0f) ? 0.0f : r1;
}

// ---------------- kernel 1: LayerNorm + QKV projection (+prep fold) ----------------
__global__ void __launch_bounds__(768) k_ln_qkv(
    const float* __restrict__ x, const float* __restrict__ n1w,
    const float* __restrict__ n1b, const float* __restrict__ wq,
    const float* __restrict__ wk, const float* __restrict__ wv,
    const float* __restrict__ wr) {
    __shared__ float xs[128 * QSTR];
    int base = blockIdx.x * 128;
    int tid = threadIdx.x;
    if (blockIdx.x == 0 && tid < CHN) {        // folded k_prep
        g_mn[tid] = 0xFFFFFFFFu;
        g_mx[tid] = 0u;
        int h = tid / 3, r = tid % 3;
        float qw = 0.f;
        for (int k = 0; k < 8; k++) {
            float s = 0.f;
            for (int d = 0; d < 32; d++) s += wr[(h * 32 + d) * 24 + r * 8 + k];
            qw += expf(fminf(s, 50.f));
        }
        g_sqrtw[tid] = sqrtf(2.f * qw);
    }
    if (tid < 128) {
        int n = base + tid;
        float r[32];
        const float4* xr = (const float4*)(x + (size_t)n * 32);
#pragma unroll
        for (int u = 0; u < 8; u++) {
            float4 v4 = xr[u];
            r[4 * u] = v4.x; r[4 * u + 1] = v4.y; r[4 * u + 2] = v4.z; r[4 * u + 3] = v4.w;
        }
        float mu = 0.f;
#pragma unroll
        for (int d = 0; d < 32; d++) mu += r[d];
        mu *= (1.0f / 32.0f);
        float var = 0.f;
#pragma unroll
        for (int d = 0; d < 32; d++) { float dd = r[d] - mu; var += dd * dd; }
        var *= (1.0f / 32.0f);
        float rs = rsqrtf(var + 1e-5f);
#pragma unroll
        for (int d = 0; d < 32; d++)
            xs[tid * QSTR + d] = (r[d] - mu) * rs * n1w[d] + n1b[d];
    }
    __syncthreads();
    int j = tid;
    int proj = j >> 8, jj = j & 255;
    const float* W = (proj == 0) ? wq : (proj == 1) ? wk : wv;
    ull wpk[16];
#pragma unroll
    for (int d = 0; d < 16; d++)
        wpk[d] = pk2(W[(2 * d) * 256 + jj], W[(2 * d + 1) * 256 + jj]);
    int h = jj >> 5, d0 = jj & 31;
    float* dst;
    int stride;
    if (proj == 0) { dst = g_qhat; stride = QSTR; }
    else if (proj == 1) { dst = g_khat; stride = QSTR; }
    else { dst = g_v; stride = DH; }
    for (int r = 0; r < 128; r++) {
        const float4* xr = (const float4*)(xs + r * QSTR);
        ull a0 = 0, a1 = 0;
#pragma unroll
        for (int u = 0; u < 8; u++) {
            float4 v4 = xr[u];
            a0 = f2fma(lo2(v4), wpk[2 * u], a0);
            a1 = f2fma(hi2(v4), wpk[2 * u + 1], a1);
        }
        float s0, s1;
        upk(f2add(a0, a1), s0, s1);
        dst[((size_t)h * NPTS + (base + r)) * stride + d0] = s0 + s1;
    }
}

// ---------------- kernel 2: hat tails + LSH hashes + min/max ----------------
__global__ void k_hash(const float* __restrict__ coords, const float* __restrict__ alpha) {
    int h = blockIdx.y;
    int n = blockIdx.x * 256 + threadIdx.x;
    float q[36], kk[36];
    float* qrow = g_qhat + ((size_t)h * NPTS + n) * QSTR;
    float* krow = g_khat + ((size_t)h * NPTS + n) * QSTR;
#pragma unroll
    for (int u = 0; u < 8; u++) {
        ((float4*)q)[u] = ((const float4*)qrow)[u];
        ((float4*)kk)[u] = ((const float4*)krow)[u];
    }
#pragma unroll
    for (int r = 0; r < 3; r++) {
        float sr = g_sqrtw[h * 3 + r] * coords[n * 3 + r];
        q[32 + r] = sr; kk[32 + r] = sr;
        qrow[32 + r] = sr; krow[32 + r] = sr;
    }
    qrow[35] = 0.f; krow[35] = 0.f;               // zero pad element
    float qh[3] = {0.f, 0.f, 0.f}, kh[3] = {0.f, 0.f, 0.f};
    const float* al = alpha + h * 105;
#pragma unroll 5
    for (int d = 0; d < 35; d++) {
        float a0 = al[d * 3 + 0], a1 = al[d * 3 + 1], a2 = al[d * 3 + 2];
        qh[0] += q[d] * a0; qh[1] += q[d] * a1; qh[2] += q[d] * a2;
        kh[0] += kk[d] * a0; kh[1] += kk[d] * a1; kh[2] += kk[d] * a2;
    }
#pragma unroll
    for (int c = 0; c < 3; c++) {
        g_qh[(size_t)(c * 8 + h) * NPTS + n] = qh[c];
        g_kh[(size_t)(c * 8 + h) * NPTS + n] = kh[c];
        float mn = fminf(qh[c], kh[c]);
        float mx = fmaxf(qh[c], kh[c]);
#pragma unroll
        for (int o = 16; o > 0; o >>= 1) {
            mn = fminf(mn, __shfl_xor_sync(0xFFFFFFFFu, mn, o));
            mx = fmaxf(mx, __shfl_xor_sync(0xFFFFFFFFu, mx, o));
        }
        if ((threadIdx.x & 31) == 0) {
            atomicMin(&g_mn[c * 8 + h], encf(mn));
            atomicMax(&g_mx[c * 8 + h], encf(mx));
        }
    }
}

// ---------------- kernel 4: build 64-bit sort keys (+hs fold) ----------------
__global__ void k_keys(const int* __restrict__ shifts) {
    int t = blockIdx.x * 256 + threadIdx.x;
    int seg = t >> 15;
    int n = t & (NPTS - 1);
    float hsv = decf(g_mx[seg]) - decf(g_mn[seg]);
    float sh = (float)shifts[t];
    float off = __fmul_rn(sh, hsv);
    g_keys[t] = ((ull)encf(__fadd_rn(g_qh[t], off)) << 32) | (unsigned)n;
    g_keys[(size_t)CHN * NPTS + t] =
        ((ull)encf(__fadd_rn(g_kh[t], off)) << 32) | (unsigned)n;
}

// ---------------- local bitonic sort of 4096-elem chunks (ascending) ----------------
// 512 threads, 8 elems/thread; element index i(s) = w*256 + s*32 + l.
template<int J>
__device__ __forceinline__ void shflp8(ull* r, int ibase, int l, int k_) {
#pragma unroll
    for (int s = 0; s < 8; s++) {
        int i = ibase + s * 32;
        bool up = ((i & k_) == 0);
        ull o = __shfl_xor_sync(0xFFFFFFFFu, r[s], J);
        bool kmin = (((l & J) == 0) == up);
        ull lo_ = (r[s] < o) ? r[s] : o;
        ull hi_ = (r[s] < o) ? o : r[s];
        r[s] = kmin ? lo_ : hi_;
    }
}
template<int JS>   // slot-pair pass, J = JS*32
__device__ __forceinline__ void slotp8(ull* r, int ibase, int k_) {
#pragma unroll
    for (int s = 0; s < 8; s++) {
        if (!(s & JS)) {
            int sp = s | JS;
            int i = ibase + s * 32;
            bool up = ((i & k_) == 0);
            if ((r[s] > r[sp]) == up) { ull t2 = r[s]; r[s] = r[sp]; r[sp] = t2; }
        }
    }
}
// all passes with J <= min(k/2, 128), descending
__device__ __forceinline__ void regpasses8(ull* r, int ibase, int l, int k_) {
    int half = k_ >> 1;
    if (half >= 128) slotp8<4>(r, ibase, k_);
    if (half >= 64)  slotp8<2>(r, ibase, k_);
    if (half >= 32)  slotp8<1>(r, ibase, k_);
    if (half >= 16)  shflp8<16>(r, ibase, l, k_);
    if (half >= 8)   shflp8<8>(r, ibase, l, k_);
    if (half >= 4)   shflp8<4>(r, ibase, l, k_);
    if (half >= 2)   shflp8<2>(r, ibase, l, k_);
    shflp8<1>(r, ibase, l, k_);
}
__device__ __forceinline__ void smem_pass4k(ull* s, int k_, int j_, int tid) {
#pragma unroll
    for (int p = 0; p < 4; p++) {
        int t = tid + p * 512;
        int i = ((t & ~(j_ - 1)) << 1) | (t & (j_ - 1));
        bool up = ((i & k_) == 0);
        ull a = s[i], b = s[i + j_];
        if ((a > b) == up) { s[i] = b; s[i + j_] = a; }
    }
}

__global__ void __launch_bounds__(512) k_sort_local4k() {
    __shared__ ull s[4096];
    size_t base = (size_t)blockIdx.x * 4096;
    int tid = threadIdx.x;
    int w = tid >> 5, l = tid & 31;
    int ibase = w * 256 + l;
    ull r[8];
#pragma unroll
    for (int s_ = 0; s_ < 8; s_++) r[s_] = g_keys[base + ibase + s_ * 32];

    for (int k_ = 2; k_ <= 256; k_ <<= 1) regpasses8(r, ibase, l, k_);

    for (int k_ = 512; k_ <= 4096; k_ <<= 1) {
#pragma unroll
        for (int s_ = 0; s_ < 8; s_++) s[ibase + s_ * 32] = r[s_];
        __syncthreads();
        for (int j_ = k_ >> 1; j_ >= 256; j_ >>= 1) {
            smem_pass4k(s, k_, j_, tid);
            __syncthreads();
        }
#pragma unroll
        for (int s_ = 0; s_ < 8; s_++) r[s_] = s[ibase + s_ * 32];
        __syncthreads();
        regpasses8(r, ibase, l, k_);   // caps at J=128 internally
    }
#pragma unroll
    for (int s_ = 0; s_ < 8; s_++) g_keys[base + ibase + s_ * 32] = r[s_];
}

// ---------------- merge-path merge pass: runs of L -> 2L ----------------
// dir=0: g_keys -> g_keys2 ; dir=1: g_keys2 -> g_keys
__global__ void __launch_bounds__(256) k_mergepath(int L, int dir) {
    const ull* __restrict__ src = dir ? g_keys2 : g_keys;
    ull* __restrict__ dst = dir ? g_keys : g_keys2;
    size_t outbase = (size_t)blockIdx.x * 4096 + (size_t)threadIdx.x * 16;
    size_t pairBase = outbase & ~((size_t)(2 * L) - 1);
    const ull* A = src + pairBase;
    const ull* B = A + L;
    int p0 = (int)(outbase - pairBase);
    int lo = p0 > L ? p0 - L : 0;
    int hi = p0 < L ? p0 : L;
    while (lo < hi) {
        int m = (lo + hi) >> 1;
        if (A[m] <= B[p0 - 1 - m]) lo = m + 1; else hi = m;
    }
    int i = lo, j = p0 - lo;
    ull* d = dst + pairBase + p0;
    ull a = (i < L) ? A[i] : ~0ull;     // keys never equal ~0 (index bits < 2^15)
    ull b = (j < L) ? B[j] : ~0ull;
#pragma unroll
    for (int t = 0; t < 16; t++) {
        bool takeA = (a <= b);
        d[t] = takeA ? a : b;
        if (takeA) { i++; a = (i < L) ? A[i] : ~0ull; }
        else       { j++; b = (j < L) ? B[j] : ~0ull; }
    }
}

// ---------------- kernel 5: bucketed attention (2 buckets/block, 2 q/thread) ----------------
// reads final sorted keys from g_keys2
__global__ void __launch_bounds__(128) k_attn() {
    extern __shared__ float sm[];
    float* ks = sm;                    // [2][128][36]
    float* vs = sm + 9216;             // [2][128][32]
    float* ksq = sm + 9216 + 8192;     // [2][128]
    int seg = blockIdx.y;
    int h = seg & 7;
    int t = threadIdx.x;
    int tb = t >> 6, tq = t & 63;
    int bucket = blockIdx.x * 2 + tb;

    const ull* kkey = g_keys2 + ((size_t)(CHN + seg)) * NPTS + bucket * BSZ;
    const ull* qkey = g_keys2 + (size_t)seg * NPTS + bucket * BSZ;

#pragma unroll
    for (int rr = 0; rr < 2; rr++) {
        int row = tq + rr * 64;
        unsigned kidx = (unsigned)kkey[row];
        const float4* kr = (const float4*)(g_khat + ((size_t)h * NPTS + kidx) * QSTR);
        float tmp[36];
#pragma unroll
        for (int u = 0; u < 9; u++) ((float4*)tmp)[u] = kr[u];
        float s2 = 0.f;
#pragma unroll
        for (int d = 0; d < 35; d++) s2 += tmp[d] * tmp[d];
        ksq[tb * 128 + row] = -0.5f * s2;
        float* kd = ks + (tb * 128 + row) * 36;
#pragma unroll
        for (int u = 0; u < 9; u++) ((float4*)kd)[u] = ((float4*)tmp)[u];
        const float4* vr = (const float4*)(g_v + ((size_t)h * NPTS + kidx) * DH);
        float* vd = vs + (tb * 128 + row) * 32;
#pragma unroll
        for (int u = 0; u < 8; u++) ((float4*)vd)[u] = vr[u];
    }

    unsigned qidxA = (unsigned)qkey[tq];
    unsigned qidxB = (unsigned)qkey[tq + 64];
    ull qAp[18], qBp[18];
    {
        const float4* qr = (const float4*)(g_qhat + ((size_t)h * NPTS + qidxA) * QSTR);
#pragma unroll
        for (int u = 0; u < 9; u++) ((float4*)qAp)[u] = qr[u];
        const float4* qr2 = (const float4*)(g_qhat + ((size_t)h * NPTS + qidxB) * QSTR);
#pragma unroll
        for (int u = 0; u < 9; u++) ((float4*)qBp)[u] = qr2[u];
    }
    float qsqA = 0.f, qsqB = 0.f;
#pragma unroll
    for (int d = 0; d < 35; d++) {
        qsqA += ((float*)qAp)[d] * ((float*)qAp)[d];
        qsqB += ((float*)qBp)[d] * ((float*)qBp)[d];
    }
    qsqA *= -0.5f; qsqB *= -0.5f;

    ull accA[16], accB[16];
#pragma unroll
    for (int p = 0; p < 16; p++) { accA[p] = 0ull; accB[p] = 0ull; }
    float denA = 0.f, denB = 0.f;
    __syncthreads();

    const float* ksb = ks + tb * 128 * 36;
    const float* vsb = vs + tb * 128 * 32;
    const float* ksqb = ksq + tb * 128;
    for (int j = 0; j < BSZ; j++) {
        ull c[18];
        const float4* krow = (const float4*)(ksb + j * 36);
#pragma unroll
        for (int u = 0; u < 9; u++) ((float4*)c)[u] = krow[u];
        ull dA0 = 0ull, dA1 = 0ull, dB0 = 0ull, dB1 = 0ull;
#pragma unroll
        for (int p = 0; p < 18; p += 2) {
            dA0 = f2fma(qAp[p], c[p], dA0);
            dA1 = f2fma(qAp[p + 1], c[p + 1], dA1);
            dB0 = f2fma(qBp[p], c[p], dB0);
            dB1 = f2fma(qBp[p + 1], c[p + 1], dB1);
        }
        float ksqv = ksqb[j];
        float a0, a1, b0, b1;
        upk(f2add(dA0, dA1), a0, a1);
        upk(f2add(dB0, dB1), b0, b1);
        float sA = a0 + a1 + qsqA + ksqv;
        float sB = b0 + b1 + qsqB + ksqv;
        float eA, eB;
        fexp2p(pk2(sA, sB), eA, eB);
        denA += eA; denB += eB;
        ull eAd = pk2(eA, eA), eBd = pk2(eB, eB);
        ull vp[16];
        const float4* vrow = (const float4*)(vsb + j * 32);
#pragma unroll
        for (int u = 0; u < 8; u++) ((float4*)vp)[u] = vrow[u];
#pragma unroll
        for (int p = 0; p < 16; p++) {
            accA[p] = f2fma(eAd, vp[p], accA[p]);
            accB[p] = f2fma(eBd, vp[p], accB[p]);
        }
    }
    float* odA = g_oscr + ((size_t)seg * NPTS + qidxA) * DH;
    float* odB = g_oscr + ((size_t)seg * NPTS + qidxB) * DH;
#pragma unroll
    for (int p = 0; p < 8; p++) {
        float o0, o1, o2, o3;
        upk(accA[2 * p], o0, o1); upk(accA[2 * p + 1], o2, o3);
        ((float4*)odA)[p] = make_float4(o0, o1, o2, o3);
    }
#pragma unroll
    for (int p = 0; p < 8; p++) {
        float o0, o1, o2, o3;
        upk(accB[2 * p], o0, o1); upk(accB[2 * p + 1], o2, o3);
        ((float4*)odB)[p] = make_float4(o0, o1, o2, o3);
    }
    g_dscr[(size_t)seg * NPTS + qidxA] = denA;
    g_dscr[(size_t)seg * NPTS + qidxB] = denB;
}

// ---------------- kernel 6: combine over hashes + normalize ----------------
__global__ void k_combine() {
    int t = blockIdx.x * 256 + threadIdx.x;
    int p = t & 7;
    int n = (t >> 3) & (NPTS - 1);
    int h = t >> 18;
    float den = g_dscr[(size_t)(0 + h) * NPTS + n] +
                g_dscr[(size_t)(8 + h) * NPTS + n] +
                g_dscr[(size_t)(16 + h) * NPTS + n] + 3e-20f;
    float4 a = ((const float4*)(g_oscr + ((size_t)(0 + h) * NPTS + n) * DH))[p];
    float4 b4 = ((const float4*)(g_oscr + ((size_t)(8 + h) * NPTS + n) * DH))[p];
    float4 c4 = ((const float4*)(g_oscr + ((size_t)(16 + h) * NPTS + n) * DH))[p];
    float inv = 1.0f / den;
    float4 o;
    o.x = (a.x + b4.x + c4.x) * inv;
    o.y = (a.y + b4.y + c4.y) * inv;
    o.z = (a.z + b4.z + c4.z) * inv;
    o.w = (a.w + b4.w + c4.w) * inv;
    ((float4*)(g_attn + (size_t)n * 256 + h * 32))[p] = o;
}

// ---------------- kernel 7: out-proj + residual + LN2 + FF(silu) + residual ----------------
__global__ void __launch_bounds__(128) k_epilogue(
    const float* __restrict__ x, const float* __restrict__ ow,
    const float* __restrict__ ob, const float* __restrict__ n2w,
    const float* __restrict__ n2b, const float* __restrict__ f1w,
    const float* __restrict__ f1b, const float* __restrict__ f2w,
    const float* __restrict__ f2b, float* __restrict__ out) {
    __shared__ float ws[256 * 32];
    __shared__ float f1sT[32 * 32];
    __shared__ float f2s[32 * 32];
    __shared__ float cs[32 * 5];
    int tid = threadIdx.x;
    for (int i = tid; i < 8192; i += 128) ws[i] = ow[i];
    for (int i = tid; i < 1024; i += 128) {
        f1sT[(i & 31) * 32 + (i >> 5)] = f1w[i];
        f2s[i] = f2w[i];
    }
    if (tid < 32) {
        cs[tid] = ob[tid]; cs[32 + tid] = n2w[tid]; cs[64 + tid] = n2b[tid];
        cs[96 + tid] = f1b[tid]; cs[128 + tid] = f2b[tid];
    }
    __syncthreads();
    int n = blockIdx.x * 128 + tid;

    ull acc2[16];
#pragma unroll
    for (int p = 0; p < 16; p++) acc2[p] = pk2(cs[2 * p], cs[2 * p + 1]);
    const float4* ar = (const float4*)(g_attn + (size_t)n * 256);
    for (int jb = 0; jb < 64; jb++) {
        float4 a = ar[jb];
        ull ad0 = pk2(a.x, a.x), ad1 = pk2(a.y, a.y);
        ull ad2 = pk2(a.z, a.z), ad3 = pk2(a.w, a.w);
        const float4* w0 = (const float4*)(ws + (jb * 4 + 0) * 32);
        const float4* w1 = (const float4*)(ws + (jb * 4 + 1) * 32);
        const float4* w2 = (const float4*)(ws + (jb * 4 + 2) * 32);
        const float4* w3 = (const float4*)(ws + (jb * 4 + 3) * 32);
#pragma unroll
        for (int p = 0; p < 8; p++) {
            float4 r0 = w0[p], r1 = w1[p], r2 = w2[p], r3 = w3[p];
            acc2[2 * p] = f2fma(ad0, lo2(r0), acc2[2 * p]);
            acc2[2 * p + 1] = f2fma(ad0, hi2(r0), acc2[2 * p + 1]);
            acc2[2 * p] = f2fma(ad1, lo2(r1), acc2[2 * p]);
            acc2[2 * p + 1] = f2fma(ad1, hi2(r1), acc2[2 * p + 1]);
            acc2[2 * p] = f2fma(ad2, lo2(r2), acc2[2 * p]);
            acc2[2 * p + 1] = f2fma(ad2, hi2(r2), acc2[2 * p + 1]);
            acc2[2 * p] = f2fma(ad3, lo2(r3), acc2[2 * p]);
            acc2[2 * p + 1] = f2fma(ad3, hi2(r3), acc2[2 * p + 1]);
        }
    }
    float acc[32];
#pragma unroll
    for (int p = 0; p < 16; p++) upk(acc2[p], acc[2 * p], acc[2 * p + 1]);

    float x2[32];
    const float4* xr = (const float4*)(x + (size_t)n * 32);
#pragma unroll
    for (int u = 0; u < 8; u++) {
        float4 xv = xr[u];
        x2[4 * u] = xv.x + acc[4 * u];
        x2[4 * u + 1] = xv.y + acc[4 * u + 1];
        x2[4 * u + 2] = xv.z + acc[4 * u + 2];
        x2[4 * u + 3] = xv.w + acc[4 * u + 3];
    }
    float mu = 0.f;
#pragma unroll
    for (int d = 0; d < 32; d++) mu += x2[d];
    mu *= (1.0f / 32.0f);
    float var = 0.f;
#pragma unroll
    for (int d = 0; d < 32; d++) { float dd = x2[d] - mu; var += dd * dd; }
    var *= (1.0f / 32.0f);
    float rs = rsqrtf(var + 1e-5f);
    float xn2[32];
#pragma unroll
    for (int d = 0; d < 32; d++)
        xn2[d] = (x2[d] - mu) * rs * cs[32 + d] + cs[64 + d];
    ull xp[16];
#pragma unroll
    for (int u = 0; u < 16; u++) xp[u] = pk2(xn2[2 * u], xn2[2 * u + 1]);
    float h1[32];
#pragma unroll 4
    for (int jj = 0; jj < 32; jj++) {
        const float4* fr = (const float4*)(f1sT + jj * 32);
        ull a0 = 0ull, a1 = 0ull;
#pragma unroll
        for (int u = 0; u < 8; u++) {
            float4 v4 = fr[u];
            a0 = f2fma(lo2(v4), xp[2 * u], a0);
            a1 = f2fma(hi2(v4), xp[2 * u + 1], a1);
        }
        float s0, s1;
        upk(f2add(a0, a1), s0, s1);
        float t2 = cs[96 + jj] + s0 + s1;
        h1[jj] = t2 / (1.0f + fexp(-t2));
    }
    ull o2[16];
#pragma unroll
    for (int p = 0; p < 16; p++) o2[p] = pk2(cs[128 + 2 * p], cs[128 + 2 * p + 1]);
#pragma unroll 4
    for (int jj = 0; jj < 32; jj++) {
        ull hd = pk2(h1[jj], h1[jj]);
        const float4* fr = (const float4*)(f2s + jj * 32);
#pragma unroll
        for (int p = 0; p < 8; p++) {
            float4 v4 = fr[p];
            o2[2 * p] = f2fma(hd, lo2(v4), o2[2 * p]);
            o2[2 * p + 1] = f2fma(hd, hi2(v4), o2[2 * p + 1]);
        }
    }
    float o[32];
#pragma unroll
    for (int p = 0; p < 16; p++) upk(o2[p], o[2 * p], o[2 * p + 1]);
    float4* orow = (float4*)(out + (size_t)n * 32);
#pragma unroll
    for (int u = 0; u < 8; u++)
        orow[u] = make_float4(x2[4 * u] + o[4 * u], x2[4 * u + 1] + o[4 * u + 1],
                              x2[4 * u + 2] + o[4 * u + 2], x2[4 * u + 3] + o[4 * u + 3]);
}

// ---------------- launcher ----------------
extern "C" void kernel_launch(void* const* d_in, const int* in_sizes, int n_in,
                              void* d_out, int out_size) {
    const float* x = (const float*)d_in[0];
    const float* coords = (const float*)d_in[1];
    const int* shifts = (const int*)d_in[2];
    const float* n1w = (const float*)d_in[3];
    const float* n1b = (const float*)d_in[4];
    const float* wq = (const float*)d_in[5];
    const float* wk = (const float*)d_in[6];
    const float* wv = (const float*)d_in[7];
    const float* wr = (const float*)d_in[8];
    const float* alpha = (const float*)d_in[9];
    const float* ow = (const float*)d_in[10];
    const float* ob = (const float*)d_in[11];
    const float* n2w = (const float*)d_in[12];
    const float* n2b = (const float*)d_in[13];
    const float* f1w = (const float*)d_in[14];
    const float* f1b = (const float*)d_in[15];
    const float* f2w = (const float*)d_in[16];
    const float* f2b = (const float*)d_in[17];
    float* out = (float*)d_out;

    cudaFuncSetAttribute(k_attn, cudaFuncAttributeMaxDynamicSharedMemorySize, 71680);

    k_ln_qkv<<<NPTS / 128, 768>>>(x, n1w, n1b, wq, wk, wv, wr);
    k_hash<<<dim3(NPTS / 256, NH), 256>>>(coords, alpha);
    k_keys<<<(CHN * NPTS) / 256, 256>>>(shifts);

    // local bitonic sort of 4096-chunks, then 3 merge-path passes
    const int TOT = 2 * CHN * NPTS;
    k_sort_local4k<<<TOT / 4096, 512>>>();
    k_mergepath<<<TOT / 4096, 256>>>(4096, 0);    // keys  -> keys2 (runs 8192)
    k_mergepath<<<TOT / 4096, 256>>>(8192, 1);    // keys2 -> keys  (runs 16384)
    k_mergepath<<<TOT / 4096, 256>>>(16384, 0);   // keys  -> keys2 (runs 32768)

    k_attn<<<dim3(NBK / 2, CHN), 128, 71680>>>();
    k_combine<<<(NH * NPTS * 8) / 256, 256>>>();
    k_epilogue<<<NPTS / 128, 128>>>(x, ow, ob, n2w, n2b, f1w, f1b, f2w, f2b, out);
}